// round 7
// baseline (speedup 1.0000x reference)
#include <cuda_runtime.h>

#define NB 16
#define MM 1024
#define DD 64
#define HH 4
#define NEG 0.2f

// Scratch (allocation-free rule: __device__ globals)
__device__ float g_K[NB*HH*MM*DD];   // [n,h,m,d]   fp32
__device__ float g_Q[NB*HH*MM*DD];   // [n,h,m,d']  tf32-rounded, d-permuted
__device__ float g_V[NB*HH*MM*DD];   // Vt [n,h,e,m'] tf32-rounded, transposed + j-permuted
__device__ float g_dx[NB*MM*HH*DD];

__device__ __forceinline__ unsigned f2tf32(float f) {
    unsigned u;
    asm("cvt.rna.tf32.f32 %0, %1;" : "=r"(u) : "f"(f));
    return u;
}

__device__ __forceinline__ void mma_tf32(float& d0, float& d1, float& d2, float& d3,
                                         unsigned a0, unsigned a1, unsigned a2, unsigned a3,
                                         unsigned b0, unsigned b1) {
    asm volatile("mma.sync.aligned.m16n8k8.row.col.f32.tf32.tf32.f32 "
                 "{%0,%1,%2,%3}, {%4,%5,%6,%7}, {%8,%9}, {%0,%1,%2,%3};"
                 : "+f"(d0), "+f"(d1), "+f"(d2), "+f"(d3)
                 : "r"(a0), "r"(a1), "r"(a2), "r"(a3), "r"(b0), "r"(b1));
}

__device__ __forceinline__ void cp16(unsigned dst_smem, const void* src) {
    asm volatile("cp.async.cg.shared.global [%0], [%1], 16;" :: "r"(dst_smem), "l"(src));
}

// d-permutation (GMEM, for B-frag float4 packing): d' = (d%4)*16 + d/4
__device__ __forceinline__ int dperm(int d) { return (d & 3)*16 + (d >> 2); }
// j-permutation matching the S c-frag column order: j = 8k+2q+r -> q*16 + 2k + r
__device__ __forceinline__ int jperm(int j) {
    return ((j >> 1) & 3)*16 + ((j >> 3) << 1) + (j & 1);
}

// Conflict-free smem block layout: 64-float row -> 4 blocks of 16 floats at
// offsets {0,24,48,72}, row stride 100 floats. Bank group of a B-frag float4
// = (25*row + 6*qc + kkp) mod 8 -> bijective over each 8-lane phase.
#define RSTR 100
#define TILEF (64*RSTR)          // floats per 64x64 tile

// ---------------------------------------------------------------------------
// Kernel 1: TF32 tensor-core K/Q/V projections, 3-term precision split.
// grid (M/512, 3*H, N), block 256 (8 warps). Weight smem loaded once
// (swizzled), reused across 4 row-tiles of 128 rows.
// ---------------------------------------------------------------------------
#define QKV_SMEM (2*TILEF*4)

__global__ __launch_bounds__(256, 2) void qkv_tc(
    const float* __restrict__ x,
    const float* __restrict__ Wk, const float* __restrict__ bk,
    const float* __restrict__ Wq, const float* __restrict__ bq,
    const float* __restrict__ Wv, const float* __restrict__ bv)
{
    extern __shared__ float sm[];
    float* Wh = sm;
    float* Wl = sm + TILEF;
    int n = blockIdx.z;
    int which = blockIdx.y / HH;
    int h = blockIdx.y % HH;
    int mbase = blockIdx.x * 512;
    const float* W; const float* bias;
    if (which == 0)      { W = Wk; bias = bk; }
    else if (which == 1) { W = Wq; bias = bq; }
    else                 { W = Wv; bias = bv; }
    int tid = threadIdx.x;
    int warp = tid >> 5, lane = tid & 31;
    int qr = lane >> 2, qc = lane & 3;

    const float* wg = W + h*DD*DD;
    #pragma unroll
    for (int i = 0; i < 16; i++) {
        int l = i*256 + tid;
        int e = l >> 6, d = l & 63;
        float w = wg[l];
        unsigned hi = f2tf32(w);
        int idx = e*RSTR + (d&3)*24 + (d>>4)*4 + ((d>>2)&3);
        Wh[idx] = __uint_as_float(hi);
        Wl[idx] = __uint_as_float(f2tf32(w - __uint_as_float(hi)));
    }
    __syncthreads();

    size_t hb = (size_t)(n*HH + h);

    for (int rt = 0; rt < 4; rt++) {
        int r0 = mbase + rt*128 + warp*16 + qr;
        const float* xg0 = x + (size_t)(n*MM + r0)*DD;
        const float* xg1 = xg0 + 8*DD;

        float xa[4][8];
        #pragma unroll
        for (int kk = 0; kk < 8; kk++) {
            xa[0][kk] = xg0[kk*8 + qc];
            xa[1][kk] = xg1[kk*8 + qc];
            xa[2][kk] = xg0[kk*8 + qc + 4];
            xa[3][kk] = xg1[kk*8 + qc + 4];
        }

        float o[8][4] = {};
        #pragma unroll
        for (int kkp = 0; kkp < 4; kkp++) {
            unsigned ah0[4], al0[4], ah1[4], al1[4];
            #pragma unroll
            for (int i = 0; i < 4; i++) {
                float v0 = xa[i][2*kkp], v1 = xa[i][2*kkp+1];
                ah0[i] = f2tf32(v0); al0[i] = f2tf32(v0 - __uint_as_float(ah0[i]));
                ah1[i] = f2tf32(v1); al1[i] = f2tf32(v1 - __uint_as_float(ah1[i]));
            }
            #pragma unroll
            for (int nt = 0; nt < 8; nt++) {
                int row = (nt*8 + qr)*RSTR + qc*24 + 4*kkp;
                float4 fh = *(const float4*)&Wh[row];
                float4 fl = *(const float4*)&Wl[row];
                unsigned bh0 = __float_as_uint(fh.x), bh1 = __float_as_uint(fh.y);
                unsigned bl0 = __float_as_uint(fl.x), bl1 = __float_as_uint(fl.y);
                mma_tf32(o[nt][0],o[nt][1],o[nt][2],o[nt][3], ah0[0],ah0[1],ah0[2],ah0[3], bh0,bh1);
                mma_tf32(o[nt][0],o[nt][1],o[nt][2],o[nt][3], ah0[0],ah0[1],ah0[2],ah0[3], bl0,bl1);
                mma_tf32(o[nt][0],o[nt][1],o[nt][2],o[nt][3], al0[0],al0[1],al0[2],al0[3], bh0,bh1);
                unsigned ch0 = __float_as_uint(fh.z), ch1 = __float_as_uint(fh.w);
                unsigned cl0 = __float_as_uint(fl.z), cl1 = __float_as_uint(fl.w);
                mma_tf32(o[nt][0],o[nt][1],o[nt][2],o[nt][3], ah1[0],ah1[1],ah1[2],ah1[3], ch0,ch1);
                mma_tf32(o[nt][0],o[nt][1],o[nt][2],o[nt][3], ah1[0],ah1[1],ah1[2],ah1[3], cl0,cl1);
                mma_tf32(o[nt][0],o[nt][1],o[nt][2],o[nt][3], al1[0],al1[1],al1[2],al1[3], ch0,ch1);
            }
        }

        if (which == 0) {
            float* Ko = g_K + hb*MM*DD;
            #pragma unroll
            for (int nt = 0; nt < 8; nt++) {
                int c0 = nt*8 + 2*qc;
                float b0 = bias[h*DD + c0], b1 = bias[h*DD + c0 + 1];
                *(float2*)&Ko[(size_t)r0*DD + c0]     = make_float2(o[nt][0]+b0, o[nt][1]+b1);
                *(float2*)&Ko[(size_t)(r0+8)*DD + c0] = make_float2(o[nt][2]+b0, o[nt][3]+b1);
            }
        } else if (which == 1) {
            float* Qo = g_Q + hb*MM*DD;
            #pragma unroll
            for (int nt = 0; nt < 8; nt++) {
                int c0 = nt*8 + 2*qc;
                float b0 = bias[h*DD + c0], b1 = bias[h*DD + c0 + 1];
                int dp = dperm(c0);
                Qo[(size_t)r0*DD + dp]          = __uint_as_float(f2tf32(o[nt][0]+b0));
                Qo[(size_t)r0*DD + dp + 16]     = __uint_as_float(f2tf32(o[nt][1]+b1));
                Qo[(size_t)(r0+8)*DD + dp]      = __uint_as_float(f2tf32(o[nt][2]+b0));
                Qo[(size_t)(r0+8)*DD + dp + 16] = __uint_as_float(f2tf32(o[nt][3]+b1));
            }
        } else {
            float* Vt = g_V + hb*DD*MM;   // [e][m']
            int mp0 = (r0 & ~63) + jperm(r0 & 63);
            int mp1 = ((r0+8) & ~63) + jperm((r0+8) & 63);
            #pragma unroll
            for (int nt = 0; nt < 8; nt++) {
                int c0 = nt*8 + 2*qc;
                float b0 = bias[h*DD + c0], b1 = bias[h*DD + c0 + 1];
                Vt[(size_t)c0*MM     + mp0] = __uint_as_float(f2tf32(o[nt][0]+b0));
                Vt[(size_t)(c0+1)*MM + mp0] = __uint_as_float(f2tf32(o[nt][1]+b1));
                Vt[(size_t)c0*MM     + mp1] = __uint_as_float(f2tf32(o[nt][2]+b0));
                Vt[(size_t)(c0+1)*MM + mp1] = __uint_as_float(f2tf32(o[nt][3]+b1));
            }
        }
    }
}

// ---------------------------------------------------------------------------
// Kernel 2: TF32 tensor-core flash attention, conflict-free swizzled smem.
// smem: Q[2], Vt[2] tiles in block layout, cp.async double-buffered.
// PV A-frags come straight from the S accumulator registers (no P smem).
// ---------------------------------------------------------------------------
#define ATTN2_SMEM (4*TILEF*4)

__global__ __launch_bounds__(256, 2) void attn_tc(const float* __restrict__ x)
{
    extern __shared__ float sm[];

    int n = blockIdx.z, h = blockIdx.y;
    int itile = blockIdx.x * 128;
    int tid = threadIdx.x;
    int warp = tid >> 5, lane = tid & 31;
    int qr = lane >> 2, qc = lane & 3;

    const float* Kg = g_K + (size_t)(n*HH + h)*MM*DD;
    const float* Qb = g_Q + (size_t)(n*HH + h)*MM*DD;
    const float* Vb = g_V + (size_t)(n*HH + h)*DD*MM;   // Vt [e][m']

    int r0 = itile + warp*16 + qr;

    // Hoist K A-fragments for the whole j-loop
    unsigned ka[8][4];
    #pragma unroll
    for (int kk = 0; kk < 8; kk++) {
        ka[kk][0] = f2tf32(Kg[(size_t)r0*DD     + kk*8 + qc    ]);
        ka[kk][1] = f2tf32(Kg[(size_t)(r0+8)*DD + kk*8 + qc    ]);
        ka[kk][2] = f2tf32(Kg[(size_t)r0*DD     + kk*8 + qc + 4]);
        ka[kk][3] = f2tf32(Kg[(size_t)(r0+8)*DD + kk*8 + qc + 4]);
    }

    float o[8][4] = {};
    float mr0 = -1e30f, mr1 = -1e30f, lr0 = 0.f, lr1 = 0.f;

    unsigned base0 = (unsigned)__cvta_generic_to_shared(sm);
    // buffers: Q0, Q1, V0, V1 each TILEF floats
    unsigned qbase[2] = { base0, base0 + TILEF*4 };
    unsigned vbase[2] = { base0 + 2*TILEF*4, base0 + 3*TILEF*4 };

    // staging map: thread -> (row, c4), STS-phase conflict-free
    int st_row = tid >> 4;
    int st_w16 = tid & 15;
    int st_c4  = ((st_w16 & 3) << 2) | (st_w16 >> 2);
    int st_col = (st_c4 >> 2)*16 + (st_c4 & 3)*4;          // gmem col base
    int st_ofs = ((st_c4 >> 2)*24 + (st_c4 & 3)*4)*4;      // smem byte offset in row

    // stage tile 0
    #pragma unroll
    for (int k = 0; k < 4; k++) {
        int row = st_row + 16*k;
        unsigned so = row*RSTR*4 + st_ofs;
        cp16(qbase[0] + so, Qb + (size_t)row*DD + st_col);
        cp16(vbase[0] + so, Vb + (size_t)row*MM + st_col);
    }
    asm volatile("cp.async.commit_group;");

    for (int jt = 0; jt < 16; jt++) {
        int buf = jt & 1;
        if (jt < 15) {
            int nb = buf ^ 1;
            const float* qg = Qb + (size_t)(jt+1)*64*DD;
            const float* vg = Vb + (jt+1)*64;
            #pragma unroll
            for (int k = 0; k < 4; k++) {
                int row = st_row + 16*k;
                unsigned so = row*RSTR*4 + st_ofs;
                cp16(qbase[nb] + so, qg + (size_t)row*DD + st_col);
                cp16(vbase[nb] + so, vg + (size_t)row*MM + st_col);
            }
            asm volatile("cp.async.commit_group;");
            asm volatile("cp.async.wait_group 1;");
        } else {
            asm volatile("cp.async.wait_group 0;");
        }
        __syncthreads();

        const float* Qc = sm + buf*TILEF;
        const float* Vc = sm + (2+buf)*TILEF;

        // ---- S = K . Q^T ----
        float s[8][4];
        #pragma unroll
        for (int nt = 0; nt < 8; nt++) {
            s[nt][0] = s[nt][1] = s[nt][2] = s[nt][3] = 0.f;
            const float* qrow = &Qc[(nt*8 + qr)*RSTR + qc*24];
            #pragma unroll
            for (int kkp = 0; kkp < 4; kkp++) {
                float4 f = *(const float4*)&qrow[4*kkp];
                mma_tf32(s[nt][0], s[nt][1], s[nt][2], s[nt][3],
                         ka[2*kkp][0], ka[2*kkp][1], ka[2*kkp][2], ka[2*kkp][3],
                         __float_as_uint(f.x), __float_as_uint(f.y));
                mma_tf32(s[nt][0], s[nt][1], s[nt][2], s[nt][3],
                         ka[2*kkp+1][0], ka[2*kkp+1][1], ka[2*kkp+1][2], ka[2*kkp+1][3],
                         __float_as_uint(f.z), __float_as_uint(f.w));
            }
        }

        // ---- leaky relu + online softmax ----
        float m0 = -1e30f, m1 = -1e30f;
        #pragma unroll
        for (int nt = 0; nt < 8; nt++) {
            #pragma unroll
            for (int c = 0; c < 4; c++)
                s[nt][c] = s[nt][c] > 0.f ? s[nt][c] : NEG*s[nt][c];
            m0 = fmaxf(m0, fmaxf(s[nt][0], s[nt][1]));
            m1 = fmaxf(m1, fmaxf(s[nt][2], s[nt][3]));
        }
        m0 = fmaxf(m0, __shfl_xor_sync(0xffffffffu, m0, 1));
        m0 = fmaxf(m0, __shfl_xor_sync(0xffffffffu, m0, 2));
        m1 = fmaxf(m1, __shfl_xor_sync(0xffffffffu, m1, 1));
        m1 = fmaxf(m1, __shfl_xor_sync(0xffffffffu, m1, 2));
        float nm0 = fmaxf(mr0, m0), nm1 = fmaxf(mr1, m1);
        float c0 = __expf(mr0 - nm0), c1 = __expf(mr1 - nm1);
        mr0 = nm0; mr1 = nm1;
        float a0 = 0.f, a1 = 0.f;
        #pragma unroll
        for (int nt = 0; nt < 8; nt++) {
            s[nt][0] = __expf(s[nt][0] - nm0);
            s[nt][1] = __expf(s[nt][1] - nm0);
            s[nt][2] = __expf(s[nt][2] - nm1);
            s[nt][3] = __expf(s[nt][3] - nm1);
            a0 += s[nt][0] + s[nt][1];
            a1 += s[nt][2] + s[nt][3];
            o[nt][0] *= c0; o[nt][1] *= c0; o[nt][2] *= c1; o[nt][3] *= c1;
        }
        a0 += __shfl_xor_sync(0xffffffffu, a0, 1);
        a0 += __shfl_xor_sync(0xffffffffu, a0, 2);
        a1 += __shfl_xor_sync(0xffffffffu, a1, 1);
        a1 += __shfl_xor_sync(0xffffffffu, a1, 2);
        lr0 = lr0*c0 + a0;
        lr1 = lr1*c1 + a1;

        // ---- O += P . V  (A-frags from s registers; V rows j-permuted) ----
        #pragma unroll
        for (int kkp = 0; kkp < 4; kkp++) {
            int k0 = 2*kkp, k1 = 2*kkp + 1;
            unsigned p00 = f2tf32(s[k0][0]), p01 = f2tf32(s[k0][2]);
            unsigned p02 = f2tf32(s[k0][1]), p03 = f2tf32(s[k0][3]);
            unsigned p10 = f2tf32(s[k1][0]), p11 = f2tf32(s[k1][2]);
            unsigned p12 = f2tf32(s[k1][1]), p13 = f2tf32(s[k1][3]);
            #pragma unroll
            for (int nt = 0; nt < 8; nt++) {
                float4 g = *(const float4*)&Vc[(nt*8 + qr)*RSTR + qc*24 + 4*kkp];
                mma_tf32(o[nt][0], o[nt][1], o[nt][2], o[nt][3],
                         p00, p01, p02, p03,
                         __float_as_uint(g.x), __float_as_uint(g.y));
                mma_tf32(o[nt][0], o[nt][1], o[nt][2], o[nt][3],
                         p10, p11, p12, p13,
                         __float_as_uint(g.z), __float_as_uint(g.w));
            }
        }
        __syncthreads();
    }

    // ---- epilogue: leaky(o/l) - x -> g_dx (N, M, H*D) ----
    float inv0 = 1.f / lr0, inv1 = 1.f / lr1;
    size_t gm0 = (size_t)(n*MM + r0);
    size_t gm1 = gm0 + 8;
    const float* x0 = x + gm0*DD;
    const float* x1 = x + gm1*DD;
    float* d0 = g_dx + gm0*(HH*DD) + h*DD;
    float* d1 = g_dx + gm1*(HH*DD) + h*DD;
    #pragma unroll
    for (int nt = 0; nt < 8; nt++) {
        int cb = nt*8 + 2*qc;
        float2 xv0 = *(const float2*)&x0[cb];
        float2 xv1 = *(const float2*)&x1[cb];
        float v00 = o[nt][0]*inv0; v00 = (v00 > 0.f ? v00 : NEG*v00) - xv0.x;
        float v01 = o[nt][1]*inv0; v01 = (v01 > 0.f ? v01 : NEG*v01) - xv0.y;
        float v10 = o[nt][2]*inv1; v10 = (v10 > 0.f ? v10 : NEG*v10) - xv1.x;
        float v11 = o[nt][3]*inv1; v11 = (v11 > 0.f ? v11 : NEG*v11) - xv1.y;
        *(float2*)&d0[cb] = make_float2(v00, v01);
        *(float2*)&d1[cb] = make_float2(v10, v11);
    }
}

// ---------------------------------------------------------------------------
// Kernel 3: decoder (fp32 SIMT, near its FMA floor).
// ---------------------------------------------------------------------------
#define DEC_SMEM ((64*256 + 64*257) * 4)

__global__ __launch_bounds__(256) void dec_kernel(
    const float* __restrict__ Wdec, const float* __restrict__ bdec,
    float* __restrict__ out)
{
    extern __shared__ float sm[];
    float* ds = sm;
    float* Ws = ds + 64*256;
    int row0 = blockIdx.x * 64;
    int tx = threadIdx.x, ty = threadIdx.y;
    int tid = ty*16 + tx;
    #pragma unroll
    for (int r = 0; r < 64; r++) {
        int l = r*256 + tid;
        ds[l] = g_dx[(size_t)row0*256 + l];
        Ws[(l>>8)*257 + (l&255)] = Wdec[l];
    }
    __syncthreads();
    float acc[4][4] = {};
    int ty4 = ty*4;
    #pragma unroll 4
    for (int c = 0; c < 256; c += 4) {
        float4 dr[4];
        #pragma unroll
        for (int a = 0; a < 4; a++)
            dr[a] = *(const float4*)&ds[(ty4+a)*256 + c];
        #pragma unroll
        for (int b = 0; b < 4; b++) {
            const float* wp = &Ws[(b*16+tx)*257 + c];
            float w0 = wp[0], w1 = wp[1], w2 = wp[2], w3 = wp[3];
            #pragma unroll
            for (int a = 0; a < 4; a++) {
                acc[a][b] = fmaf(dr[a].x, w0, acc[a][b]);
                acc[a][b] = fmaf(dr[a].y, w1, acc[a][b]);
                acc[a][b] = fmaf(dr[a].z, w2, acc[a][b]);
                acc[a][b] = fmaf(dr[a].w, w3, acc[a][b]);
            }
        }
    }
    #pragma unroll
    for (int b = 0; b < 4; b++) {
        float bb = bdec[b*16 + tx];
        #pragma unroll
        for (int a = 0; a < 4; a++)
            out[(size_t)(row0 + ty4 + a)*DD + b*16 + tx] = acc[a][b] + bb;
    }
}

// ---------------------------------------------------------------------------
extern "C" void kernel_launch(void* const* d_in, const int* in_sizes, int n_in,
                              void* d_out, int out_size)
{
    const float* x    = (const float*)d_in[0];
    // d_in[1] = edge (unused)
    const float* Wk   = (const float*)d_in[2];
    const float* bk   = (const float*)d_in[3];
    const float* Wq   = (const float*)d_in[4];
    const float* bq   = (const float*)d_in[5];
    const float* Wv   = (const float*)d_in[6];
    const float* bv   = (const float*)d_in[7];
    const float* Wdec = (const float*)d_in[8];
    const float* bdec = (const float*)d_in[9];
    float* out = (float*)d_out;

    cudaFuncSetAttribute(qkv_tc,     cudaFuncAttributeMaxDynamicSharedMemorySize, QKV_SMEM);
    cudaFuncSetAttribute(attn_tc,    cudaFuncAttributeMaxDynamicSharedMemorySize, ATTN2_SMEM);
    cudaFuncSetAttribute(dec_kernel, cudaFuncAttributeMaxDynamicSharedMemorySize, DEC_SMEM);

    qkv_tc<<<dim3(MM/512, 3*HH, NB), 256, QKV_SMEM>>>(x, Wk, bk, Wq, bq, Wv, bv);
    attn_tc<<<dim3(MM/128, HH, NB), 256, ATTN2_SMEM>>>(x);
    dec_kernel<<<NB*MM/64, dim3(16,16), DEC_SMEM>>>(Wdec, bdec, out);
}

// round 9
// speedup vs baseline: 1.7403x; 1.7403x over previous
#include <cuda_runtime.h>

#define NB 16
#define MM 1024
#define DD 64
#define HH 4
#define NEG 0.2f

// Scratch (allocation-free rule: __device__ globals)
__device__ float g_K[NB*HH*MM*DD];   // [n,h,m,d]   fp32
__device__ float g_Q[NB*HH*MM*DD];   // [n,h,m,d']  tf32-rounded, d-permuted
__device__ float g_V[NB*HH*MM*DD];   // Vt [n,h,e,m'] tf32-rounded, transposed + j-permuted
__device__ float g_dx[NB*MM*HH*DD];

__device__ __forceinline__ unsigned f2tf32(float f) {
    unsigned u;
    asm("cvt.rna.tf32.f32 %0, %1;" : "=r"(u) : "f"(f));
    return u;
}

__device__ __forceinline__ void mma_tf32(float& d0, float& d1, float& d2, float& d3,
                                         unsigned a0, unsigned a1, unsigned a2, unsigned a3,
                                         unsigned b0, unsigned b1) {
    asm volatile("mma.sync.aligned.m16n8k8.row.col.f32.tf32.tf32.f32 "
                 "{%0,%1,%2,%3}, {%4,%5,%6,%7}, {%8,%9}, {%0,%1,%2,%3};"
                 : "+f"(d0), "+f"(d1), "+f"(d2), "+f"(d3)
                 : "r"(a0), "r"(a1), "r"(a2), "r"(a3), "r"(b0), "r"(b1));
}

__device__ __forceinline__ void cp16(unsigned dst_smem, const void* src) {
    asm volatile("cp.async.cg.shared.global [%0], [%1], 16;" :: "r"(dst_smem), "l"(src));
}

// d-permutation (GMEM, for B-frag float4 packing): d' = (d%4)*16 + d/4
__device__ __forceinline__ int dperm(int d) { return (d & 3)*16 + (d >> 2); }
// j-permutation matching the S c-frag column order: j = 8k+2q+r -> q*16 + 2k + r
__device__ __forceinline__ int jperm(int j) {
    return ((j >> 1) & 3)*16 + ((j >> 3) << 1) + (j & 1);
}

// Conflict-free compact smem layout: 64-float row -> 4 blocks of 16 floats at
// offsets {0,20,40,60}, row stride 80 floats (320B). B-frag float4 bank-group
// = (4*row + 5*qc + kkp) mod 8 -> bijective over each 8-lane LDS phase.
#define SSTR 80
#define TILEF (64*SSTR)          // 5120 floats = 20.5KB per 64x64 tile

// ---------------------------------------------------------------------------
// Kernel 1: TF32 tensor-core K/Q/V projections, 3-term precision split.
// grid (M/128, 3*H, N), block 256 (8 warps, 16 rows each).  (R6 structure)
// ---------------------------------------------------------------------------
__global__ __launch_bounds__(256, 2) void qkv_tc(
    const float* __restrict__ x,
    const float* __restrict__ Wk, const float* __restrict__ bk,
    const float* __restrict__ Wq, const float* __restrict__ bq,
    const float* __restrict__ Wv, const float* __restrict__ bv)
{
    __shared__ float Wh[TILEF];
    __shared__ float Wl[TILEF];
    int n = blockIdx.z;
    int which = blockIdx.y / HH;
    int h = blockIdx.y % HH;
    int mtile = blockIdx.x * 128;
    const float* W; const float* bias;
    if (which == 0)      { W = Wk; bias = bk; }
    else if (which == 1) { W = Wq; bias = bq; }
    else                 { W = Wv; bias = bv; }
    int tid = threadIdx.x;
    int warp = tid >> 5, lane = tid & 31;
    int qr = lane >> 2, qc = lane & 3;

    const float* wg = W + h*DD*DD;
    #pragma unroll
    for (int i = 0; i < 16; i++) {
        int l = i*256 + tid;
        int e = l >> 6, d = l & 63;
        float w = wg[l];
        unsigned hi = f2tf32(w);
        // dperm(d) -> block layout: block q = d&3 (at 20q), within = d>>2
        int idx = e*SSTR + (d&3)*20 + (d>>2);
        Wh[idx] = __uint_as_float(hi);
        Wl[idx] = __uint_as_float(f2tf32(w - __uint_as_float(hi)));
    }
    __syncthreads();

    int r0 = mtile + warp*16 + qr;
    const float* xg0 = x + (size_t)(n*MM + r0)*DD;
    const float* xg1 = xg0 + 8*DD;

    float xa[4][8];
    #pragma unroll
    for (int kk = 0; kk < 8; kk++) {
        xa[0][kk] = xg0[kk*8 + qc];
        xa[1][kk] = xg1[kk*8 + qc];
        xa[2][kk] = xg0[kk*8 + qc + 4];
        xa[3][kk] = xg1[kk*8 + qc + 4];
    }

    float o[8][4] = {};
    #pragma unroll
    for (int kkp = 0; kkp < 4; kkp++) {
        unsigned ah0[4], al0[4], ah1[4], al1[4];
        #pragma unroll
        for (int i = 0; i < 4; i++) {
            float v0 = xa[i][2*kkp], v1 = xa[i][2*kkp+1];
            ah0[i] = f2tf32(v0); al0[i] = f2tf32(v0 - __uint_as_float(ah0[i]));
            ah1[i] = f2tf32(v1); al1[i] = f2tf32(v1 - __uint_as_float(ah1[i]));
        }
        #pragma unroll
        for (int nt = 0; nt < 8; nt++) {
            int row = (nt*8 + qr)*SSTR + qc*20 + 4*kkp;
            float4 fh = *(const float4*)&Wh[row];
            float4 fl = *(const float4*)&Wl[row];
            unsigned bh0 = __float_as_uint(fh.x), bh1 = __float_as_uint(fh.y);
            unsigned bl0 = __float_as_uint(fl.x), bl1 = __float_as_uint(fl.y);
            mma_tf32(o[nt][0],o[nt][1],o[nt][2],o[nt][3], ah0[0],ah0[1],ah0[2],ah0[3], bh0,bh1);
            mma_tf32(o[nt][0],o[nt][1],o[nt][2],o[nt][3], ah0[0],ah0[1],ah0[2],ah0[3], bl0,bl1);
            mma_tf32(o[nt][0],o[nt][1],o[nt][2],o[nt][3], al0[0],al0[1],al0[2],al0[3], bh0,bh1);
            unsigned ch0 = __float_as_uint(fh.z), ch1 = __float_as_uint(fh.w);
            unsigned cl0 = __float_as_uint(fl.z), cl1 = __float_as_uint(fl.w);
            mma_tf32(o[nt][0],o[nt][1],o[nt][2],o[nt][3], ah1[0],ah1[1],ah1[2],ah1[3], ch0,ch1);
            mma_tf32(o[nt][0],o[nt][1],o[nt][2],o[nt][3], ah1[0],ah1[1],ah1[2],ah1[3], cl0,cl1);
            mma_tf32(o[nt][0],o[nt][1],o[nt][2],o[nt][3], al1[0],al1[1],al1[2],al1[3], ch0,ch1);
        }
    }

    // epilogue
    size_t hb = (size_t)(n*HH + h);
    if (which == 0) {
        float* Ko = g_K + hb*MM*DD;
        #pragma unroll
        for (int nt = 0; nt < 8; nt++) {
            int c0 = nt*8 + 2*qc;
            float b0 = bias[h*DD + c0], b1 = bias[h*DD + c0 + 1];
            *(float2*)&Ko[(size_t)r0*DD + c0]     = make_float2(o[nt][0]+b0, o[nt][1]+b1);
            *(float2*)&Ko[(size_t)(r0+8)*DD + c0] = make_float2(o[nt][2]+b0, o[nt][3]+b1);
        }
    } else if (which == 1) {
        float* Qo = g_Q + hb*MM*DD;
        #pragma unroll
        for (int nt = 0; nt < 8; nt++) {
            int c0 = nt*8 + 2*qc;
            float b0 = bias[h*DD + c0], b1 = bias[h*DD + c0 + 1];
            int dp = dperm(c0);
            Qo[(size_t)r0*DD + dp]          = __uint_as_float(f2tf32(o[nt][0]+b0));
            Qo[(size_t)r0*DD + dp + 16]     = __uint_as_float(f2tf32(o[nt][1]+b1));
            Qo[(size_t)(r0+8)*DD + dp]      = __uint_as_float(f2tf32(o[nt][2]+b0));
            Qo[(size_t)(r0+8)*DD + dp + 16] = __uint_as_float(f2tf32(o[nt][3]+b1));
        }
    } else {
        float* Vt = g_V + hb*DD*MM;   // [e][m']
        int mp0 = (r0 & ~63) + jperm(r0 & 63);
        int mp1 = ((r0+8) & ~63) + jperm((r0+8) & 63);
        #pragma unroll
        for (int nt = 0; nt < 8; nt++) {
            int c0 = nt*8 + 2*qc;
            float b0 = bias[h*DD + c0], b1 = bias[h*DD + c0 + 1];
            Vt[(size_t)c0*MM     + mp0] = __uint_as_float(f2tf32(o[nt][0]+b0));
            Vt[(size_t)(c0+1)*MM + mp0] = __uint_as_float(f2tf32(o[nt][1]+b1));
            Vt[(size_t)c0*MM     + mp1] = __uint_as_float(f2tf32(o[nt][2]+b0));
            Vt[(size_t)(c0+1)*MM + mp1] = __uint_as_float(f2tf32(o[nt][3]+b1));
        }
    }
}

// ---------------------------------------------------------------------------
// Kernel 2: TF32 tensor-core flash attention, conflict-free compact smem.
// smem: Q[2], Vt[2] tiles (SSTR=80 block layout), cp.async double-buffered.
// PV A-frags come straight from the S accumulator registers (no P smem).
// ---------------------------------------------------------------------------
#define ATTN2_SMEM (4*TILEF*4)    // 81.9 KB -> 2 CTAs/SM

__global__ __launch_bounds__(256, 2) void attn_tc(const float* __restrict__ x)
{
    extern __shared__ float sm[];

    int n = blockIdx.z, h = blockIdx.y;
    int itile = blockIdx.x * 128;
    int tid = threadIdx.x;
    int warp = tid >> 5, lane = tid & 31;
    int qr = lane >> 2, qc = lane & 3;

    const float* Kg = g_K + (size_t)(n*HH + h)*MM*DD;
    const float* Qb = g_Q + (size_t)(n*HH + h)*MM*DD;
    const float* Vb = g_V + (size_t)(n*HH + h)*DD*MM;   // Vt [e][m']

    int r0 = itile + warp*16 + qr;

    // Hoist K A-fragments for the whole j-loop
    unsigned ka[8][4];
    #pragma unroll
    for (int kk = 0; kk < 8; kk++) {
        ka[kk][0] = f2tf32(Kg[(size_t)r0*DD     + kk*8 + qc    ]);
        ka[kk][1] = f2tf32(Kg[(size_t)(r0+8)*DD + kk*8 + qc    ]);
        ka[kk][2] = f2tf32(Kg[(size_t)r0*DD     + kk*8 + qc + 4]);
        ka[kk][3] = f2tf32(Kg[(size_t)(r0+8)*DD + kk*8 + qc + 4]);
    }

    float o[8][4] = {};
    float mr0 = -1e30f, mr1 = -1e30f, lr0 = 0.f, lr1 = 0.f;

    unsigned base0 = (unsigned)__cvta_generic_to_shared(sm);
    unsigned qbase[2] = { base0, base0 + TILEF*4 };
    unsigned vbase[2] = { base0 + 2*TILEF*4, base0 + 3*TILEF*4 };

    // staging map (STS-phase rainbow): lane -> (q, rowbit, kchunk)
    int sg_q  = lane & 3;
    int sg_rb = (lane >> 2) & 1;
    int sg_k  = lane >> 3;                       // 0..3
    int sg_col = sg_q*16 + sg_k*4;               // gmem float col
    int sg_ofs = (sg_q*20 + sg_k*4)*4;           // smem byte offset in row

    // stage tile 0
    #pragma unroll
    for (int rnd = 0; rnd < 4; rnd++) {
        int row = rnd*16 + 2*warp + sg_rb;
        unsigned so = row*SSTR*4 + sg_ofs;
        cp16(qbase[0] + so, Qb + (size_t)row*DD + sg_col);
        cp16(vbase[0] + so, Vb + (size_t)row*MM + sg_col);
    }
    asm volatile("cp.async.commit_group;");

    for (int jt = 0; jt < 16; jt++) {
        int buf = jt & 1;
        if (jt < 15) {
            int nb = buf ^ 1;
            const float* qg = Qb + (size_t)(jt+1)*64*DD;
            const float* vg = Vb + (jt+1)*64;
            #pragma unroll
            for (int rnd = 0; rnd < 4; rnd++) {
                int row = rnd*16 + 2*warp + sg_rb;
                unsigned so = row*SSTR*4 + sg_ofs;
                cp16(qbase[nb] + so, qg + (size_t)row*DD + sg_col);
                cp16(vbase[nb] + so, vg + (size_t)row*MM + sg_col);
            }
            asm volatile("cp.async.commit_group;");
            asm volatile("cp.async.wait_group 1;");
        } else {
            asm volatile("cp.async.wait_group 0;");
        }
        __syncthreads();

        const float* Qc = sm + buf*TILEF;
        const float* Vc = sm + (2+buf)*TILEF;

        // ---- S = K . Q^T ----
        float s[8][4];
        #pragma unroll
        for (int nt = 0; nt < 8; nt++) {
            s[nt][0] = s[nt][1] = s[nt][2] = s[nt][3] = 0.f;
            const float* qrow = &Qc[(nt*8 + qr)*SSTR + qc*20];
            #pragma unroll
            for (int kkp = 0; kkp < 4; kkp++) {
                float4 f = *(const float4*)&qrow[4*kkp];
                mma_tf32(s[nt][0], s[nt][1], s[nt][2], s[nt][3],
                         ka[2*kkp][0], ka[2*kkp][1], ka[2*kkp][2], ka[2*kkp][3],
                         __float_as_uint(f.x), __float_as_uint(f.y));
                mma_tf32(s[nt][0], s[nt][1], s[nt][2], s[nt][3],
                         ka[2*kkp+1][0], ka[2*kkp+1][1], ka[2*kkp+1][2], ka[2*kkp+1][3],
                         __float_as_uint(f.z), __float_as_uint(f.w));
            }
        }

        // ---- leaky relu + online softmax ----
        float m0 = -1e30f, m1 = -1e30f;
        #pragma unroll
        for (int nt = 0; nt < 8; nt++) {
            #pragma unroll
            for (int c = 0; c < 4; c++)
                s[nt][c] = s[nt][c] > 0.f ? s[nt][c] : NEG*s[nt][c];
            m0 = fmaxf(m0, fmaxf(s[nt][0], s[nt][1]));
            m1 = fmaxf(m1, fmaxf(s[nt][2], s[nt][3]));
        }
        m0 = fmaxf(m0, __shfl_xor_sync(0xffffffffu, m0, 1));
        m0 = fmaxf(m0, __shfl_xor_sync(0xffffffffu, m0, 2));
        m1 = fmaxf(m1, __shfl_xor_sync(0xffffffffu, m1, 1));
        m1 = fmaxf(m1, __shfl_xor_sync(0xffffffffu, m1, 2));
        float nm0 = fmaxf(mr0, m0), nm1 = fmaxf(mr1, m1);
        float c0 = __expf(mr0 - nm0), c1 = __expf(mr1 - nm1);
        mr0 = nm0; mr1 = nm1;
        float a0 = 0.f, a1 = 0.f;
        #pragma unroll
        for (int nt = 0; nt < 8; nt++) {
            s[nt][0] = __expf(s[nt][0] - nm0);
            s[nt][1] = __expf(s[nt][1] - nm0);
            s[nt][2] = __expf(s[nt][2] - nm1);
            s[nt][3] = __expf(s[nt][3] - nm1);
            a0 += s[nt][0] + s[nt][1];
            a1 += s[nt][2] + s[nt][3];
            o[nt][0] *= c0; o[nt][1] *= c0; o[nt][2] *= c1; o[nt][3] *= c1;
        }
        a0 += __shfl_xor_sync(0xffffffffu, a0, 1);
        a0 += __shfl_xor_sync(0xffffffffu, a0, 2);
        a1 += __shfl_xor_sync(0xffffffffu, a1, 1);
        a1 += __shfl_xor_sync(0xffffffffu, a1, 2);
        lr0 = lr0*c0 + a0;
        lr1 = lr1*c1 + a1;

        // ---- O += P . V  (A-frags from s registers; V rows j-permuted) ----
        #pragma unroll
        for (int kkp = 0; kkp < 4; kkp++) {
            int k0 = 2*kkp, k1 = 2*kkp + 1;
            unsigned p00 = f2tf32(s[k0][0]), p01 = f2tf32(s[k0][2]);
            unsigned p02 = f2tf32(s[k0][1]), p03 = f2tf32(s[k0][3]);
            unsigned p10 = f2tf32(s[k1][0]), p11 = f2tf32(s[k1][2]);
            unsigned p12 = f2tf32(s[k1][1]), p13 = f2tf32(s[k1][3]);
            #pragma unroll
            for (int nt = 0; nt < 8; nt++) {
                float4 g = *(const float4*)&Vc[(nt*8 + qr)*SSTR + qc*20 + 4*kkp];
                mma_tf32(o[nt][0], o[nt][1], o[nt][2], o[nt][3],
                         p00, p01, p02, p03,
                         __float_as_uint(g.x), __float_as_uint(g.y));
                mma_tf32(o[nt][0], o[nt][1], o[nt][2], o[nt][3],
                         p10, p11, p12, p13,
                         __float_as_uint(g.z), __float_as_uint(g.w));
            }
        }
        __syncthreads();
    }

    // ---- epilogue: leaky(o/l) - x -> g_dx (N, M, H*D) ----
    float inv0 = 1.f / lr0, inv1 = 1.f / lr1;
    size_t gm0 = (size_t)(n*MM + r0);
    size_t gm1 = gm0 + 8;
    const float* x0 = x + gm0*DD;
    const float* x1 = x + gm1*DD;
    float* d0 = g_dx + gm0*(HH*DD) + h*DD;
    float* d1 = g_dx + gm1*(HH*DD) + h*DD;
    #pragma unroll
    for (int nt = 0; nt < 8; nt++) {
        int cb = nt*8 + 2*qc;
        float2 xv0 = *(const float2*)&x0[cb];
        float2 xv1 = *(const float2*)&x1[cb];
        float v00 = o[nt][0]*inv0; v00 = (v00 > 0.f ? v00 : NEG*v00) - xv0.x;
        float v01 = o[nt][1]*inv0; v01 = (v01 > 0.f ? v01 : NEG*v01) - xv0.y;
        float v10 = o[nt][2]*inv1; v10 = (v10 > 0.f ? v10 : NEG*v10) - xv1.x;
        float v11 = o[nt][3]*inv1; v11 = (v11 > 0.f ? v11 : NEG*v11) - xv1.y;
        *(float2*)&d0[cb] = make_float2(v00, v01);
        *(float2*)&d1[cb] = make_float2(v10, v11);
    }
}

// ---------------------------------------------------------------------------
// Kernel 3: decoder (fp32 SIMT, near its FMA floor).
// ---------------------------------------------------------------------------
#define DEC_SMEM ((64*256 + 64*257) * 4)

__global__ __launch_bounds__(256) void dec_kernel(
    const float* __restrict__ Wdec, const float* __restrict__ bdec,
    float* __restrict__ out)
{
    extern __shared__ float sm[];
    float* ds = sm;
    float* Ws = ds + 64*256;
    int row0 = blockIdx.x * 64;
    int tx = threadIdx.x, ty = threadIdx.y;
    int tid = ty*16 + tx;
    #pragma unroll
    for (int r = 0; r < 64; r++) {
        int l = r*256 + tid;
        ds[l] = g_dx[(size_t)row0*256 + l];
        Ws[(l>>8)*257 + (l&255)] = Wdec[l];
    }
    __syncthreads();
    float acc[4][4] = {};
    int ty4 = ty*4;
    #pragma unroll 4
    for (int c = 0; c < 256; c += 4) {
        float4 dr[4];
        #pragma unroll
        for (int a = 0; a < 4; a++)
            dr[a] = *(const float4*)&ds[(ty4+a)*256 + c];
        #pragma unroll
        for (int b = 0; b < 4; b++) {
            const float* wp = &Ws[(b*16+tx)*257 + c];
            float w0 = wp[0], w1 = wp[1], w2 = wp[2], w3 = wp[3];
            #pragma unroll
            for (int a = 0; a < 4; a++) {
                acc[a][b] = fmaf(dr[a].x, w0, acc[a][b]);
                acc[a][b] = fmaf(dr[a].y, w1, acc[a][b]);
                acc[a][b] = fmaf(dr[a].z, w2, acc[a][b]);
                acc[a][b] = fmaf(dr[a].w, w3, acc[a][b]);
            }
        }
    }
    #pragma unroll
    for (int b = 0; b < 4; b++) {
        float bb = bdec[b*16 + tx];
        #pragma unroll
        for (int a = 0; a < 4; a++)
            out[(size_t)(row0 + ty4 + a)*DD + b*16 + tx] = acc[a][b] + bb;
    }
}

// ---------------------------------------------------------------------------
extern "C" void kernel_launch(void* const* d_in, const int* in_sizes, int n_in,
                              void* d_out, int out_size)
{
    const float* x    = (const float*)d_in[0];
    // d_in[1] = edge (unused)
    const float* Wk   = (const float*)d_in[2];
    const float* bk   = (const float*)d_in[3];
    const float* Wq   = (const float*)d_in[4];
    const float* bq   = (const float*)d_in[5];
    const float* Wv   = (const float*)d_in[6];
    const float* bv   = (const float*)d_in[7];
    const float* Wdec = (const float*)d_in[8];
    const float* bdec = (const float*)d_in[9];
    float* out = (float*)d_out;

    cudaFuncSetAttribute(attn_tc,    cudaFuncAttributeMaxDynamicSharedMemorySize, ATTN2_SMEM);
    cudaFuncSetAttribute(dec_kernel, cudaFuncAttributeMaxDynamicSharedMemorySize, DEC_SMEM);

    qkv_tc<<<dim3(MM/128, 3*HH, NB), 256>>>(x, Wk, bk, Wq, bq, Wv, bv);
    attn_tc<<<dim3(MM/128, HH, NB), 256, ATTN2_SMEM>>>(x);
    dec_kernel<<<NB*MM/64, dim3(16,16), DEC_SMEM>>>(Wdec, bdec, out);
}

// round 10
// speedup vs baseline: 1.8247x; 1.0485x over previous
#include <cuda_runtime.h>

#define NB 16
#define MM 1024
#define DD 64
#define HH 4
#define NEG 0.2f

// Scratch (allocation-free rule: __device__ globals)
__device__ float g_K[NB*HH*MM*DD];   // [n,h,m,d]   fp32
__device__ float g_Q[NB*HH*MM*DD];   // [n,h,m,d']  tf32-rounded, d-permuted
__device__ float g_V[NB*HH*MM*DD];   // Vt [n,h,e,m'] tf32-rounded, transposed + j-permuted
__device__ float g_dx[NB*MM*HH*DD];

__device__ __forceinline__ unsigned f2tf32(float f) {
    unsigned u;
    asm("cvt.rna.tf32.f32 %0, %1;" : "=r"(u) : "f"(f));
    return u;
}

__device__ __forceinline__ void mma_tf32(float& d0, float& d1, float& d2, float& d3,
                                         unsigned a0, unsigned a1, unsigned a2, unsigned a3,
                                         unsigned b0, unsigned b1) {
    asm volatile("mma.sync.aligned.m16n8k8.row.col.f32.tf32.tf32.f32 "
                 "{%0,%1,%2,%3}, {%4,%5,%6,%7}, {%8,%9}, {%0,%1,%2,%3};"
                 : "+f"(d0), "+f"(d1), "+f"(d2), "+f"(d3)
                 : "r"(a0), "r"(a1), "r"(a2), "r"(a3), "r"(b0), "r"(b1));
}

__device__ __forceinline__ void cp16(unsigned dst_smem, const void* src) {
    asm volatile("cp.async.cg.shared.global [%0], [%1], 16;" :: "r"(dst_smem), "l"(src));
}

// d-permutation (GMEM, for B-frag float4 packing): d' = (d%4)*16 + d/4
__device__ __forceinline__ int dperm(int d) { return (d & 3)*16 + (d >> 2); }
// j-permutation matching the S c-frag column order: j = 8k+2q+r -> q*16 + 2k + r
__device__ __forceinline__ int jperm(int j) {
    return ((j >> 1) & 3)*16 + ((j >> 3) << 1) + (j & 1);
}

// Conflict-free compact smem layout: 64-float row -> 4 blocks of 16 floats at
// offsets {0,20,40,60}, row stride 80 floats (320B). B-frag float4 bank-group
// = (4*row + 5*qc + kkp) mod 8 -> bijective over each 8-lane LDS phase.
#define SSTR 80
#define TILEF (64*SSTR)          // 5120 floats = 20.5KB per 64x64 tile

// ---------------------------------------------------------------------------
// Kernel 1: TF32 tensor-core K/Q/V projections, 3-term precision split.
// grid (M/128, 3*H, N), block 256 (8 warps, 16 rows each).  (unchanged R9)
// ---------------------------------------------------------------------------
__global__ __launch_bounds__(256, 2) void qkv_tc(
    const float* __restrict__ x,
    const float* __restrict__ Wk, const float* __restrict__ bk,
    const float* __restrict__ Wq, const float* __restrict__ bq,
    const float* __restrict__ Wv, const float* __restrict__ bv)
{
    __shared__ float Wh[TILEF];
    __shared__ float Wl[TILEF];
    int n = blockIdx.z;
    int which = blockIdx.y / HH;
    int h = blockIdx.y % HH;
    int mtile = blockIdx.x * 128;
    const float* W; const float* bias;
    if (which == 0)      { W = Wk; bias = bk; }
    else if (which == 1) { W = Wq; bias = bq; }
    else                 { W = Wv; bias = bv; }
    int tid = threadIdx.x;
    int warp = tid >> 5, lane = tid & 31;
    int qr = lane >> 2, qc = lane & 3;

    const float* wg = W + h*DD*DD;
    #pragma unroll
    for (int i = 0; i < 16; i++) {
        int l = i*256 + tid;
        int e = l >> 6, d = l & 63;
        float w = wg[l];
        unsigned hi = f2tf32(w);
        int idx = e*SSTR + (d&3)*20 + (d>>2);
        Wh[idx] = __uint_as_float(hi);
        Wl[idx] = __uint_as_float(f2tf32(w - __uint_as_float(hi)));
    }
    __syncthreads();

    int r0 = mtile + warp*16 + qr;
    const float* xg0 = x + (size_t)(n*MM + r0)*DD;
    const float* xg1 = xg0 + 8*DD;

    float xa[4][8];
    #pragma unroll
    for (int kk = 0; kk < 8; kk++) {
        xa[0][kk] = xg0[kk*8 + qc];
        xa[1][kk] = xg1[kk*8 + qc];
        xa[2][kk] = xg0[kk*8 + qc + 4];
        xa[3][kk] = xg1[kk*8 + qc + 4];
    }

    float o[8][4] = {};
    #pragma unroll
    for (int kkp = 0; kkp < 4; kkp++) {
        unsigned ah0[4], al0[4], ah1[4], al1[4];
        #pragma unroll
        for (int i = 0; i < 4; i++) {
            float v0 = xa[i][2*kkp], v1 = xa[i][2*kkp+1];
            ah0[i] = f2tf32(v0); al0[i] = f2tf32(v0 - __uint_as_float(ah0[i]));
            ah1[i] = f2tf32(v1); al1[i] = f2tf32(v1 - __uint_as_float(ah1[i]));
        }
        #pragma unroll
        for (int nt = 0; nt < 8; nt++) {
            int row = (nt*8 + qr)*SSTR + qc*20 + 4*kkp;
            float4 fh = *(const float4*)&Wh[row];
            float4 fl = *(const float4*)&Wl[row];
            unsigned bh0 = __float_as_uint(fh.x), bh1 = __float_as_uint(fh.y);
            unsigned bl0 = __float_as_uint(fl.x), bl1 = __float_as_uint(fl.y);
            mma_tf32(o[nt][0],o[nt][1],o[nt][2],o[nt][3], ah0[0],ah0[1],ah0[2],ah0[3], bh0,bh1);
            mma_tf32(o[nt][0],o[nt][1],o[nt][2],o[nt][3], ah0[0],ah0[1],ah0[2],ah0[3], bl0,bl1);
            mma_tf32(o[nt][0],o[nt][1],o[nt][2],o[nt][3], al0[0],al0[1],al0[2],al0[3], bh0,bh1);
            unsigned ch0 = __float_as_uint(fh.z), ch1 = __float_as_uint(fh.w);
            unsigned cl0 = __float_as_uint(fl.z), cl1 = __float_as_uint(fl.w);
            mma_tf32(o[nt][0],o[nt][1],o[nt][2],o[nt][3], ah1[0],ah1[1],ah1[2],ah1[3], ch0,ch1);
            mma_tf32(o[nt][0],o[nt][1],o[nt][2],o[nt][3], ah1[0],ah1[1],ah1[2],ah1[3], cl0,cl1);
            mma_tf32(o[nt][0],o[nt][1],o[nt][2],o[nt][3], al1[0],al1[1],al1[2],al1[3], ch0,ch1);
        }
    }

    // epilogue
    size_t hb = (size_t)(n*HH + h);
    if (which == 0) {
        float* Ko = g_K + hb*MM*DD;
        #pragma unroll
        for (int nt = 0; nt < 8; nt++) {
            int c0 = nt*8 + 2*qc;
            float b0 = bias[h*DD + c0], b1 = bias[h*DD + c0 + 1];
            *(float2*)&Ko[(size_t)r0*DD + c0]     = make_float2(o[nt][0]+b0, o[nt][1]+b1);
            *(float2*)&Ko[(size_t)(r0+8)*DD + c0] = make_float2(o[nt][2]+b0, o[nt][3]+b1);
        }
    } else if (which == 1) {
        float* Qo = g_Q + hb*MM*DD;
        #pragma unroll
        for (int nt = 0; nt < 8; nt++) {
            int c0 = nt*8 + 2*qc;
            float b0 = bias[h*DD + c0], b1 = bias[h*DD + c0 + 1];
            int dp = dperm(c0);
            Qo[(size_t)r0*DD + dp]          = __uint_as_float(f2tf32(o[nt][0]+b0));
            Qo[(size_t)r0*DD + dp + 16]     = __uint_as_float(f2tf32(o[nt][1]+b1));
            Qo[(size_t)(r0+8)*DD + dp]      = __uint_as_float(f2tf32(o[nt][2]+b0));
            Qo[(size_t)(r0+8)*DD + dp + 16] = __uint_as_float(f2tf32(o[nt][3]+b1));
        }
    } else {
        float* Vt = g_V + hb*DD*MM;   // [e][m']
        int mp0 = (r0 & ~63) + jperm(r0 & 63);
        int mp1 = ((r0+8) & ~63) + jperm((r0+8) & 63);
        #pragma unroll
        for (int nt = 0; nt < 8; nt++) {
            int c0 = nt*8 + 2*qc;
            float b0 = bias[h*DD + c0], b1 = bias[h*DD + c0 + 1];
            Vt[(size_t)c0*MM     + mp0] = __uint_as_float(f2tf32(o[nt][0]+b0));
            Vt[(size_t)(c0+1)*MM + mp0] = __uint_as_float(f2tf32(o[nt][1]+b1));
            Vt[(size_t)c0*MM     + mp1] = __uint_as_float(f2tf32(o[nt][2]+b0));
            Vt[(size_t)(c0+1)*MM + mp1] = __uint_as_float(f2tf32(o[nt][3]+b1));
        }
    }
}

// ---------------------------------------------------------------------------
// Kernel 2: TF32 flash attention, 4 warps x 32 rows (B-frag amortized 2x).
// Each LDS.128 B-frag feeds 4 mma (2 k-steps x 2 i-frags) -> half the
// smem crossbar traffic of the 8x16 version. smem layout unchanged.
// ---------------------------------------------------------------------------
#define ATTN2_SMEM (4*TILEF*4)    // 81.9 KB -> 2 CTAs/SM

__global__ __launch_bounds__(128, 2) void attn_tc(const float* __restrict__ x)
{
    extern __shared__ float sm[];

    int n = blockIdx.z, h = blockIdx.y;
    int itile = blockIdx.x * 128;
    int tid = threadIdx.x;
    int warp = tid >> 5, lane = tid & 31;
    int qr = lane >> 2, qc = lane & 3;

    const float* Kg = g_K + (size_t)(n*HH + h)*MM*DD;
    const float* Qb = g_Q + (size_t)(n*HH + h)*MM*DD;
    const float* Vb = g_V + (size_t)(n*HH + h)*DD*MM;   // Vt [e][m']

    // warp owns 32 rows: frag f covers rows rf0 = itile + warp*32 + f*16 + qr (+8)
    int rbase = itile + warp*32 + qr;

    // Hoist K A-fragments for both i-frags
    unsigned ka[2][8][4];
    #pragma unroll
    for (int f = 0; f < 2; f++) {
        int r0 = rbase + f*16;
        #pragma unroll
        for (int kk = 0; kk < 8; kk++) {
            ka[f][kk][0] = f2tf32(Kg[(size_t)r0*DD     + kk*8 + qc    ]);
            ka[f][kk][1] = f2tf32(Kg[(size_t)(r0+8)*DD + kk*8 + qc    ]);
            ka[f][kk][2] = f2tf32(Kg[(size_t)r0*DD     + kk*8 + qc + 4]);
            ka[f][kk][3] = f2tf32(Kg[(size_t)(r0+8)*DD + kk*8 + qc + 4]);
        }
    }

    float o[2][8][4] = {};
    float mr[2][2], lr[2][2];
    #pragma unroll
    for (int f = 0; f < 2; f++) { mr[f][0] = mr[f][1] = -1e30f; lr[f][0] = lr[f][1] = 0.f; }

    unsigned base0 = (unsigned)__cvta_generic_to_shared(sm);
    unsigned qbase[2] = { base0, base0 + TILEF*4 };
    unsigned vbase[2] = { base0 + 2*TILEF*4, base0 + 3*TILEF*4 };

    // staging map (STS-phase rainbow): lane -> (q, rowbit, kchunk); 128 threads
    int sg_q  = lane & 3;
    int sg_rb = (lane >> 2) & 1;
    int sg_k  = lane >> 3;                       // 0..3
    int sg_col = sg_q*16 + sg_k*4;               // gmem float col
    int sg_ofs = (sg_q*20 + sg_k*4)*4;           // smem byte offset in row

    // stage tile 0: rows = rnd*8 + (2*warp + sg_rb), rnd 0..7
    #pragma unroll
    for (int rnd = 0; rnd < 8; rnd++) {
        int row = rnd*8 + 2*warp + sg_rb;
        unsigned so = row*SSTR*4 + sg_ofs;
        cp16(qbase[0] + so, Qb + (size_t)row*DD + sg_col);
        cp16(vbase[0] + so, Vb + (size_t)row*MM + sg_col);
    }
    asm volatile("cp.async.commit_group;");

    for (int jt = 0; jt < 16; jt++) {
        int buf = jt & 1;
        if (jt < 15) {
            int nb = buf ^ 1;
            const float* qg = Qb + (size_t)(jt+1)*64*DD;
            const float* vg = Vb + (jt+1)*64;
            #pragma unroll
            for (int rnd = 0; rnd < 8; rnd++) {
                int row = rnd*8 + 2*warp + sg_rb;
                unsigned so = row*SSTR*4 + sg_ofs;
                cp16(qbase[nb] + so, qg + (size_t)row*DD + sg_col);
                cp16(vbase[nb] + so, vg + (size_t)row*MM + sg_col);
            }
            asm volatile("cp.async.commit_group;");
            asm volatile("cp.async.wait_group 1;");
        } else {
            asm volatile("cp.async.wait_group 0;");
        }
        __syncthreads();

        const float* Qc = sm + buf*TILEF;
        const float* Vc = sm + (2+buf)*TILEF;

        // ---- S = K . Q^T  (one B-frag -> 4 mma: 2 k-steps x 2 i-frags) ----
        float s[2][8][4];
        #pragma unroll
        for (int nt = 0; nt < 8; nt++) {
            s[0][nt][0] = s[0][nt][1] = s[0][nt][2] = s[0][nt][3] = 0.f;
            s[1][nt][0] = s[1][nt][1] = s[1][nt][2] = s[1][nt][3] = 0.f;
            const float* qrow = &Qc[(nt*8 + qr)*SSTR + qc*20];
            #pragma unroll
            for (int kkp = 0; kkp < 4; kkp++) {
                float4 g = *(const float4*)&qrow[4*kkp];
                unsigned b0 = __float_as_uint(g.x), b1 = __float_as_uint(g.y);
                unsigned b2 = __float_as_uint(g.z), b3 = __float_as_uint(g.w);
                #pragma unroll
                for (int f = 0; f < 2; f++) {
                    mma_tf32(s[f][nt][0], s[f][nt][1], s[f][nt][2], s[f][nt][3],
                             ka[f][2*kkp][0], ka[f][2*kkp][1], ka[f][2*kkp][2], ka[f][2*kkp][3],
                             b0, b1);
                    mma_tf32(s[f][nt][0], s[f][nt][1], s[f][nt][2], s[f][nt][3],
                             ka[f][2*kkp+1][0], ka[f][2*kkp+1][1], ka[f][2*kkp+1][2], ka[f][2*kkp+1][3],
                             b2, b3);
                }
            }
        }

        // ---- leaky relu + online softmax (per i-frag) ----
        #pragma unroll
        for (int f = 0; f < 2; f++) {
            float m0 = -1e30f, m1 = -1e30f;
            #pragma unroll
            for (int nt = 0; nt < 8; nt++) {
                #pragma unroll
                for (int c = 0; c < 4; c++)
                    s[f][nt][c] = s[f][nt][c] > 0.f ? s[f][nt][c] : NEG*s[f][nt][c];
                m0 = fmaxf(m0, fmaxf(s[f][nt][0], s[f][nt][1]));
                m1 = fmaxf(m1, fmaxf(s[f][nt][2], s[f][nt][3]));
            }
            m0 = fmaxf(m0, __shfl_xor_sync(0xffffffffu, m0, 1));
            m0 = fmaxf(m0, __shfl_xor_sync(0xffffffffu, m0, 2));
            m1 = fmaxf(m1, __shfl_xor_sync(0xffffffffu, m1, 1));
            m1 = fmaxf(m1, __shfl_xor_sync(0xffffffffu, m1, 2));
            float nm0 = fmaxf(mr[f][0], m0), nm1 = fmaxf(mr[f][1], m1);
            float c0 = __expf(mr[f][0] - nm0), c1 = __expf(mr[f][1] - nm1);
            mr[f][0] = nm0; mr[f][1] = nm1;
            float a0 = 0.f, a1 = 0.f;
            #pragma unroll
            for (int nt = 0; nt < 8; nt++) {
                s[f][nt][0] = __expf(s[f][nt][0] - nm0);
                s[f][nt][1] = __expf(s[f][nt][1] - nm0);
                s[f][nt][2] = __expf(s[f][nt][2] - nm1);
                s[f][nt][3] = __expf(s[f][nt][3] - nm1);
                a0 += s[f][nt][0] + s[f][nt][1];
                a1 += s[f][nt][2] + s[f][nt][3];
                o[f][nt][0] *= c0; o[f][nt][1] *= c0; o[f][nt][2] *= c1; o[f][nt][3] *= c1;
            }
            a0 += __shfl_xor_sync(0xffffffffu, a0, 1);
            a0 += __shfl_xor_sync(0xffffffffu, a0, 2);
            a1 += __shfl_xor_sync(0xffffffffu, a1, 1);
            a1 += __shfl_xor_sync(0xffffffffu, a1, 2);
            lr[f][0] = lr[f][0]*c0 + a0;
            lr[f][1] = lr[f][1]*c1 + a1;
        }

        // ---- O += P . V  (one B-frag -> 4 mma across k-steps x i-frags) ----
        #pragma unroll
        for (int kkp = 0; kkp < 4; kkp++) {
            int k0 = 2*kkp, k1 = 2*kkp + 1;
            unsigned p[2][2][4];
            #pragma unroll
            for (int f = 0; f < 2; f++) {
                p[f][0][0] = f2tf32(s[f][k0][0]); p[f][0][1] = f2tf32(s[f][k0][2]);
                p[f][0][2] = f2tf32(s[f][k0][1]); p[f][0][3] = f2tf32(s[f][k0][3]);
                p[f][1][0] = f2tf32(s[f][k1][0]); p[f][1][1] = f2tf32(s[f][k1][2]);
                p[f][1][2] = f2tf32(s[f][k1][1]); p[f][1][3] = f2tf32(s[f][k1][3]);
            }
            #pragma unroll
            for (int nt = 0; nt < 8; nt++) {
                float4 g = *(const float4*)&Vc[(nt*8 + qr)*SSTR + qc*20 + 4*kkp];
                unsigned b0 = __float_as_uint(g.x), b1 = __float_as_uint(g.y);
                unsigned b2 = __float_as_uint(g.z), b3 = __float_as_uint(g.w);
                #pragma unroll
                for (int f = 0; f < 2; f++) {
                    mma_tf32(o[f][nt][0], o[f][nt][1], o[f][nt][2], o[f][nt][3],
                             p[f][0][0], p[f][0][1], p[f][0][2], p[f][0][3], b0, b1);
                    mma_tf32(o[f][nt][0], o[f][nt][1], o[f][nt][2], o[f][nt][3],
                             p[f][1][0], p[f][1][1], p[f][1][2], p[f][1][3], b2, b3);
                }
            }
        }
        __syncthreads();
    }

    // ---- epilogue: leaky(o/l) - x -> g_dx (N, M, H*D) ----
    #pragma unroll
    for (int f = 0; f < 2; f++) {
        float inv0 = 1.f / lr[f][0], inv1 = 1.f / lr[f][1];
        size_t gm0 = (size_t)(n*MM + rbase + f*16);
        size_t gm1 = gm0 + 8;
        const float* x0 = x + gm0*DD;
        const float* x1 = x + gm1*DD;
        float* d0 = g_dx + gm0*(HH*DD) + h*DD;
        float* d1 = g_dx + gm1*(HH*DD) + h*DD;
        #pragma unroll
        for (int nt = 0; nt < 8; nt++) {
            int cb = nt*8 + 2*qc;
            float2 xv0 = *(const float2*)&x0[cb];
            float2 xv1 = *(const float2*)&x1[cb];
            float v00 = o[f][nt][0]*inv0; v00 = (v00 > 0.f ? v00 : NEG*v00) - xv0.x;
            float v01 = o[f][nt][1]*inv0; v01 = (v01 > 0.f ? v01 : NEG*v01) - xv0.y;
            float v10 = o[f][nt][2]*inv1; v10 = (v10 > 0.f ? v10 : NEG*v10) - xv1.x;
            float v11 = o[f][nt][3]*inv1; v11 = (v11 > 0.f ? v11 : NEG*v11) - xv1.y;
            *(float2*)&d0[cb] = make_float2(v00, v01);
            *(float2*)&d1[cb] = make_float2(v10, v11);
        }
    }
}

// ---------------------------------------------------------------------------
// Kernel 3: decoder (fp32 SIMT, near its FMA floor).  (unchanged)
// ---------------------------------------------------------------------------
#define DEC_SMEM ((64*256 + 64*257) * 4)

__global__ __launch_bounds__(256) void dec_kernel(
    const float* __restrict__ Wdec, const float* __restrict__ bdec,
    float* __restrict__ out)
{
    extern __shared__ float sm[];
    float* ds = sm;
    float* Ws = ds + 64*256;
    int row0 = blockIdx.x * 64;
    int tx = threadIdx.x, ty = threadIdx.y;
    int tid = ty*16 + tx;
    #pragma unroll
    for (int r = 0; r < 64; r++) {
        int l = r*256 + tid;
        ds[l] = g_dx[(size_t)row0*256 + l];
        Ws[(l>>8)*257 + (l&255)] = Wdec[l];
    }
    __syncthreads();
    float acc[4][4] = {};
    int ty4 = ty*4;
    #pragma unroll 4
    for (int c = 0; c < 256; c += 4) {
        float4 dr[4];
        #pragma unroll
        for (int a = 0; a < 4; a++)
            dr[a] = *(const float4*)&ds[(ty4+a)*256 + c];
        #pragma unroll
        for (int b = 0; b < 4; b++) {
            const float* wp = &Ws[(b*16+tx)*257 + c];
            float w0 = wp[0], w1 = wp[1], w2 = wp[2], w3 = wp[3];
            #pragma unroll
            for (int a = 0; a < 4; a++) {
                acc[a][b] = fmaf(dr[a].x, w0, acc[a][b]);
                acc[a][b] = fmaf(dr[a].y, w1, acc[a][b]);
                acc[a][b] = fmaf(dr[a].z, w2, acc[a][b]);
                acc[a][b] = fmaf(dr[a].w, w3, acc[a][b]);
            }
        }
    }
    #pragma unroll
    for (int b = 0; b < 4; b++) {
        float bb = bdec[b*16 + tx];
        #pragma unroll
        for (int a = 0; a < 4; a++)
            out[(size_t)(row0 + ty4 + a)*DD + b*16 + tx] = acc[a][b] + bb;
    }
}

// ---------------------------------------------------------------------------
extern "C" void kernel_launch(void* const* d_in, const int* in_sizes, int n_in,
                              void* d_out, int out_size)
{
    const float* x    = (const float*)d_in[0];
    // d_in[1] = edge (unused)
    const float* Wk   = (const float*)d_in[2];
    const float* bk   = (const float*)d_in[3];
    const float* Wq   = (const float*)d_in[4];
    const float* bq   = (const float*)d_in[5];
    const float* Wv   = (const float*)d_in[6];
    const float* bv   = (const float*)d_in[7];
    const float* Wdec = (const float*)d_in[8];
    const float* bdec = (const float*)d_in[9];
    float* out = (float*)d_out;

    cudaFuncSetAttribute(attn_tc,    cudaFuncAttributeMaxDynamicSharedMemorySize, ATTN2_SMEM);
    cudaFuncSetAttribute(dec_kernel, cudaFuncAttributeMaxDynamicSharedMemorySize, DEC_SMEM);

    qkv_tc<<<dim3(MM/128, 3*HH, NB), 256>>>(x, Wk, bk, Wq, bq, Wv, bv);
    attn_tc<<<dim3(MM/128, HH, NB), 128, ATTN2_SMEM>>>(x);
    dec_kernel<<<NB*MM/64, dim3(16,16), DEC_SMEM>>>(Wdec, bdec, out);
}

// round 11
// speedup vs baseline: 1.8599x; 1.0193x over previous
#include <cuda_runtime.h>

#define NB 16
#define MM 1024
#define DD 64
#define HH 4
#define NEG 0.2f
#define ESHIFT 20.0f

// Scratch (allocation-free rule: __device__ globals)
__device__ float g_K[NB*HH*MM*DD];   // [n,h,m,d]   fp32
__device__ float g_Q[NB*HH*MM*DD];   // [n,h,m,d']  tf32-rounded, d-permuted
__device__ float g_V[NB*HH*MM*DD];   // Vt [n,h,e,m'] tf32-rounded, transposed + j-permuted
__device__ float g_dx[NB*MM*HH*DD];

// Conflict-free compact smem layout: 64-float row -> 4 blocks of 16 floats at
// offsets {0,20,40,60}, row stride 80 floats (320B). B-frag float4 bank-group
// = (4*row + 5*qc + kkp) mod 8 -> bijective over each 8-lane LDS phase.
#define SSTR 80
#define TILEF (64*SSTR)          // 5120 floats = 20.5KB per 64x64 tile

// Pre-split, pre-swizzled projection weights: [which*HH + h] -> TILEF floats
__device__ float g_Wh[12*TILEF];
__device__ float g_Wl[12*TILEF];

__device__ __forceinline__ unsigned f2tf32(float f) {
    unsigned u;
    asm("cvt.rna.tf32.f32 %0, %1;" : "=r"(u) : "f"(f));
    return u;
}

__device__ __forceinline__ void mma_tf32(float& d0, float& d1, float& d2, float& d3,
                                         unsigned a0, unsigned a1, unsigned a2, unsigned a3,
                                         unsigned b0, unsigned b1) {
    asm volatile("mma.sync.aligned.m16n8k8.row.col.f32.tf32.tf32.f32 "
                 "{%0,%1,%2,%3}, {%4,%5,%6,%7}, {%8,%9}, {%0,%1,%2,%3};"
                 : "+f"(d0), "+f"(d1), "+f"(d2), "+f"(d3)
                 : "r"(a0), "r"(a1), "r"(a2), "r"(a3), "r"(b0), "r"(b1));
}

__device__ __forceinline__ void cp16(unsigned dst_smem, const void* src) {
    asm volatile("cp.async.cg.shared.global [%0], [%1], 16;" :: "r"(dst_smem), "l"(src));
}

// d-permutation (GMEM, for B-frag float4 packing): d' = (d%4)*16 + d/4
__device__ __forceinline__ int dperm(int d) { return (d & 3)*16 + (d >> 2); }
// j-permutation matching the S c-frag column order: j = 8k+2q+r -> q*16 + 2k + r
__device__ __forceinline__ int jperm(int j) {
    return ((j >> 1) & 3)*16 + ((j >> 3) << 1) + (j & 1);
}

// ---------------------------------------------------------------------------
// Kernel 0: weight prep — split W into tf32 hi/lo and store swizzled.
// grid 12 (which*HH + h), block 256. Runs once per launch (~2-3 us).
// ---------------------------------------------------------------------------
__global__ __launch_bounds__(256) void wprep(
    const float* __restrict__ Wk,
    const float* __restrict__ Wq,
    const float* __restrict__ Wv)
{
    int bid = blockIdx.x;
    int which = bid / HH, h = bid % HH;
    const float* W = (which == 0) ? Wk : (which == 1) ? Wq : Wv;
    float* oh = g_Wh + (size_t)bid*TILEF;
    float* ol = g_Wl + (size_t)bid*TILEF;
    for (int l = threadIdx.x; l < DD*DD; l += 256) {
        int e = l >> 6, d = l & 63;
        float w = W[h*DD*DD + l];
        unsigned hi = f2tf32(w);
        int idx = e*SSTR + (d&3)*20 + (d>>2);
        oh[idx] = __uint_as_float(hi);
        ol[idx] = __uint_as_float(f2tf32(w - __uint_as_float(hi)));
    }
}

// ---------------------------------------------------------------------------
// Kernel 1: TF32 tensor-core K/Q/V projections, 3-term precision split.
// grid (M/128, 3*H, N), block 256. W smem now bulk cp.async from g_Wh/g_Wl
// (no cvt, no scatter in the prologue). Output bit-identical to R10.
// ---------------------------------------------------------------------------
__global__ __launch_bounds__(256, 2) void qkv_tc(
    const float* __restrict__ x,
    const float* __restrict__ bk,
    const float* __restrict__ bq,
    const float* __restrict__ bv)
{
    __shared__ float Wh[TILEF];
    __shared__ float Wl[TILEF];
    int n = blockIdx.z;
    int which = blockIdx.y / HH;
    int h = blockIdx.y % HH;
    int mtile = blockIdx.x * 128;
    const float* bias = (which == 0) ? bk : (which == 1) ? bq : bv;
    int tid = threadIdx.x;
    int warp = tid >> 5, lane = tid & 31;
    int qr = lane >> 2, qc = lane & 3;

    {
        unsigned swh = (unsigned)__cvta_generic_to_shared(Wh);
        unsigned swl = (unsigned)__cvta_generic_to_shared(Wl);
        const float* srcH = g_Wh + (size_t)blockIdx.y*TILEF;
        const float* srcL = g_Wl + (size_t)blockIdx.y*TILEF;
        #pragma unroll
        for (int r = 0; r < 5; r++) {
            int l4 = r*256 + tid;
            cp16(swh + l4*16, srcH + l4*4);
            cp16(swl + l4*16, srcL + l4*4);
        }
        asm volatile("cp.async.commit_group;");
    }

    int r0 = mtile + warp*16 + qr;
    const float* xg0 = x + (size_t)(n*MM + r0)*DD;
    const float* xg1 = xg0 + 8*DD;

    float xa[4][8];
    #pragma unroll
    for (int kk = 0; kk < 8; kk++) {
        xa[0][kk] = xg0[kk*8 + qc];
        xa[1][kk] = xg1[kk*8 + qc];
        xa[2][kk] = xg0[kk*8 + qc + 4];
        xa[3][kk] = xg1[kk*8 + qc + 4];
    }

    asm volatile("cp.async.wait_group 0;");
    __syncthreads();

    float o[8][4] = {};
    #pragma unroll
    for (int kkp = 0; kkp < 4; kkp++) {
        unsigned ah0[4], al0[4], ah1[4], al1[4];
        #pragma unroll
        for (int i = 0; i < 4; i++) {
            float v0 = xa[i][2*kkp], v1 = xa[i][2*kkp+1];
            ah0[i] = f2tf32(v0); al0[i] = f2tf32(v0 - __uint_as_float(ah0[i]));
            ah1[i] = f2tf32(v1); al1[i] = f2tf32(v1 - __uint_as_float(ah1[i]));
        }
        #pragma unroll
        for (int nt = 0; nt < 8; nt++) {
            int row = (nt*8 + qr)*SSTR + qc*20 + 4*kkp;
            float4 fh = *(const float4*)&Wh[row];
            float4 fl = *(const float4*)&Wl[row];
            unsigned bh0 = __float_as_uint(fh.x), bh1 = __float_as_uint(fh.y);
            unsigned bl0 = __float_as_uint(fl.x), bl1 = __float_as_uint(fl.y);
            mma_tf32(o[nt][0],o[nt][1],o[nt][2],o[nt][3], ah0[0],ah0[1],ah0[2],ah0[3], bh0,bh1);
            mma_tf32(o[nt][0],o[nt][1],o[nt][2],o[nt][3], ah0[0],ah0[1],ah0[2],ah0[3], bl0,bl1);
            mma_tf32(o[nt][0],o[nt][1],o[nt][2],o[nt][3], al0[0],al0[1],al0[2],al0[3], bh0,bh1);
            unsigned ch0 = __float_as_uint(fh.z), ch1 = __float_as_uint(fh.w);
            unsigned cl0 = __float_as_uint(fl.z), cl1 = __float_as_uint(fl.w);
            mma_tf32(o[nt][0],o[nt][1],o[nt][2],o[nt][3], ah1[0],ah1[1],ah1[2],ah1[3], ch0,ch1);
            mma_tf32(o[nt][0],o[nt][1],o[nt][2],o[nt][3], ah1[0],ah1[1],ah1[2],ah1[3], cl0,cl1);
            mma_tf32(o[nt][0],o[nt][1],o[nt][2],o[nt][3], al1[0],al1[1],al1[2],al1[3], ch0,ch1);
        }
    }

    // epilogue
    size_t hb = (size_t)(n*HH + h);
    if (which == 0) {
        float* Ko = g_K + hb*MM*DD;
        #pragma unroll
        for (int nt = 0; nt < 8; nt++) {
            int c0 = nt*8 + 2*qc;
            float b0 = bias[h*DD + c0], b1 = bias[h*DD + c0 + 1];
            *(float2*)&Ko[(size_t)r0*DD + c0]     = make_float2(o[nt][0]+b0, o[nt][1]+b1);
            *(float2*)&Ko[(size_t)(r0+8)*DD + c0] = make_float2(o[nt][2]+b0, o[nt][3]+b1);
        }
    } else if (which == 1) {
        float* Qo = g_Q + hb*MM*DD;
        #pragma unroll
        for (int nt = 0; nt < 8; nt++) {
            int c0 = nt*8 + 2*qc;
            float b0 = bias[h*DD + c0], b1 = bias[h*DD + c0 + 1];
            int dp = dperm(c0);
            Qo[(size_t)r0*DD + dp]          = __uint_as_float(f2tf32(o[nt][0]+b0));
            Qo[(size_t)r0*DD + dp + 16]     = __uint_as_float(f2tf32(o[nt][1]+b1));
            Qo[(size_t)(r0+8)*DD + dp]      = __uint_as_float(f2tf32(o[nt][2]+b0));
            Qo[(size_t)(r0+8)*DD + dp + 16] = __uint_as_float(f2tf32(o[nt][3]+b1));
        }
    } else {
        float* Vt = g_V + hb*DD*MM;   // [e][m']
        int mp0 = (r0 & ~63) + jperm(r0 & 63);
        int mp1 = ((r0+8) & ~63) + jperm((r0+8) & 63);
        #pragma unroll
        for (int nt = 0; nt < 8; nt++) {
            int c0 = nt*8 + 2*qc;
            float b0 = bias[h*DD + c0], b1 = bias[h*DD + c0 + 1];
            Vt[(size_t)c0*MM     + mp0] = __uint_as_float(f2tf32(o[nt][0]+b0));
            Vt[(size_t)(c0+1)*MM + mp0] = __uint_as_float(f2tf32(o[nt][1]+b1));
            Vt[(size_t)c0*MM     + mp1] = __uint_as_float(f2tf32(o[nt][2]+b0));
            Vt[(size_t)(c0+1)*MM + mp1] = __uint_as_float(f2tf32(o[nt][3]+b1));
        }
    }
}

// ---------------------------------------------------------------------------
// Kernel 2: TF32 flash attention, 4 warps x 32 rows, FIXED-SHIFT softmax.
// No running max, no o-rescale, no per-jt shuffle chains: exp(s - 20) is
// overflow-safe for S ~ N(0,64); lr accumulated per-thread, reduced once.
// ---------------------------------------------------------------------------
#define ATTN2_SMEM (4*TILEF*4)    // 81.9 KB -> 2 CTAs/SM

__global__ __launch_bounds__(128, 2) void attn_tc(const float* __restrict__ x)
{
    extern __shared__ float sm[];

    int n = blockIdx.z, h = blockIdx.y;
    int itile = blockIdx.x * 128;
    int tid = threadIdx.x;
    int warp = tid >> 5, lane = tid & 31;
    int qr = lane >> 2, qc = lane & 3;

    const float* Kg = g_K + (size_t)(n*HH + h)*MM*DD;
    const float* Qb = g_Q + (size_t)(n*HH + h)*MM*DD;
    const float* Vb = g_V + (size_t)(n*HH + h)*DD*MM;   // Vt [e][m']

    int rbase = itile + warp*32 + qr;

    // Hoist K A-fragments for both i-frags
    unsigned ka[2][8][4];
    #pragma unroll
    for (int f = 0; f < 2; f++) {
        int r0 = rbase + f*16;
        #pragma unroll
        for (int kk = 0; kk < 8; kk++) {
            ka[f][kk][0] = f2tf32(Kg[(size_t)r0*DD     + kk*8 + qc    ]);
            ka[f][kk][1] = f2tf32(Kg[(size_t)(r0+8)*DD + kk*8 + qc    ]);
            ka[f][kk][2] = f2tf32(Kg[(size_t)r0*DD     + kk*8 + qc + 4]);
            ka[f][kk][3] = f2tf32(Kg[(size_t)(r0+8)*DD + kk*8 + qc + 4]);
        }
    }

    float o[2][8][4] = {};
    float lr[2][2] = {};          // per-thread partial row sums

    unsigned base0 = (unsigned)__cvta_generic_to_shared(sm);
    unsigned qbase[2] = { base0, base0 + TILEF*4 };
    unsigned vbase[2] = { base0 + 2*TILEF*4, base0 + 3*TILEF*4 };

    // staging map (STS-phase rainbow): lane -> (q, rowbit, kchunk); 128 threads
    int sg_q  = lane & 3;
    int sg_rb = (lane >> 2) & 1;
    int sg_k  = lane >> 3;                       // 0..3
    int sg_col = sg_q*16 + sg_k*4;               // gmem float col
    int sg_ofs = (sg_q*20 + sg_k*4)*4;           // smem byte offset in row

    // stage tile 0
    #pragma unroll
    for (int rnd = 0; rnd < 8; rnd++) {
        int row = rnd*8 + 2*warp + sg_rb;
        unsigned so = row*SSTR*4 + sg_ofs;
        cp16(qbase[0] + so, Qb + (size_t)row*DD + sg_col);
        cp16(vbase[0] + so, Vb + (size_t)row*MM + sg_col);
    }
    asm volatile("cp.async.commit_group;");

    for (int jt = 0; jt < 16; jt++) {
        int buf = jt & 1;
        if (jt < 15) {
            int nb = buf ^ 1;
            const float* qg = Qb + (size_t)(jt+1)*64*DD;
            const float* vg = Vb + (jt+1)*64;
            #pragma unroll
            for (int rnd = 0; rnd < 8; rnd++) {
                int row = rnd*8 + 2*warp + sg_rb;
                unsigned so = row*SSTR*4 + sg_ofs;
                cp16(qbase[nb] + so, qg + (size_t)row*DD + sg_col);
                cp16(vbase[nb] + so, vg + (size_t)row*MM + sg_col);
            }
            asm volatile("cp.async.commit_group;");
            asm volatile("cp.async.wait_group 1;");
        } else {
            asm volatile("cp.async.wait_group 0;");
        }
        __syncthreads();

        const float* Qc = sm + buf*TILEF;
        const float* Vc = sm + (2+buf)*TILEF;

        // ---- S = K . Q^T  (one B-frag -> 4 mma: 2 k-steps x 2 i-frags) ----
        float s[2][8][4];
        #pragma unroll
        for (int nt = 0; nt < 8; nt++) {
            s[0][nt][0] = s[0][nt][1] = s[0][nt][2] = s[0][nt][3] = 0.f;
            s[1][nt][0] = s[1][nt][1] = s[1][nt][2] = s[1][nt][3] = 0.f;
            const float* qrow = &Qc[(nt*8 + qr)*SSTR + qc*20];
            #pragma unroll
            for (int kkp = 0; kkp < 4; kkp++) {
                float4 g = *(const float4*)&qrow[4*kkp];
                unsigned b0 = __float_as_uint(g.x), b1 = __float_as_uint(g.y);
                unsigned b2 = __float_as_uint(g.z), b3 = __float_as_uint(g.w);
                #pragma unroll
                for (int f = 0; f < 2; f++) {
                    mma_tf32(s[f][nt][0], s[f][nt][1], s[f][nt][2], s[f][nt][3],
                             ka[f][2*kkp][0], ka[f][2*kkp][1], ka[f][2*kkp][2], ka[f][2*kkp][3],
                             b0, b1);
                    mma_tf32(s[f][nt][0], s[f][nt][1], s[f][nt][2], s[f][nt][3],
                             ka[f][2*kkp+1][0], ka[f][2*kkp+1][1], ka[f][2*kkp+1][2], ka[f][2*kkp+1][3],
                             b2, b3);
                }
            }
        }

        // ---- leaky relu + fixed-shift exp (no max tracking, no rescale) ----
        #pragma unroll
        for (int f = 0; f < 2; f++) {
            #pragma unroll
            for (int nt = 0; nt < 8; nt++) {
                #pragma unroll
                for (int c = 0; c < 4; c++) {
                    float sv = s[f][nt][c];
                    sv = sv > 0.f ? sv : NEG*sv;
                    s[f][nt][c] = __expf(sv - ESHIFT);
                }
                lr[f][0] += s[f][nt][0] + s[f][nt][1];
                lr[f][1] += s[f][nt][2] + s[f][nt][3];
            }
        }

        // ---- O += P . V  (A-frags from s registers; V rows j-permuted) ----
        #pragma unroll
        for (int kkp = 0; kkp < 4; kkp++) {
            int k0 = 2*kkp, k1 = 2*kkp + 1;
            unsigned p[2][2][4];
            #pragma unroll
            for (int f = 0; f < 2; f++) {
                p[f][0][0] = f2tf32(s[f][k0][0]); p[f][0][1] = f2tf32(s[f][k0][2]);
                p[f][0][2] = f2tf32(s[f][k0][1]); p[f][0][3] = f2tf32(s[f][k0][3]);
                p[f][1][0] = f2tf32(s[f][k1][0]); p[f][1][1] = f2tf32(s[f][k1][2]);
                p[f][1][2] = f2tf32(s[f][k1][1]); p[f][1][3] = f2tf32(s[f][k1][3]);
            }
            #pragma unroll
            for (int nt = 0; nt < 8; nt++) {
                float4 g = *(const float4*)&Vc[(nt*8 + qr)*SSTR + qc*20 + 4*kkp];
                unsigned b0 = __float_as_uint(g.x), b1 = __float_as_uint(g.y);
                unsigned b2 = __float_as_uint(g.z), b3 = __float_as_uint(g.w);
                #pragma unroll
                for (int f = 0; f < 2; f++) {
                    mma_tf32(o[f][nt][0], o[f][nt][1], o[f][nt][2], o[f][nt][3],
                             p[f][0][0], p[f][0][1], p[f][0][2], p[f][0][3], b0, b1);
                    mma_tf32(o[f][nt][0], o[f][nt][1], o[f][nt][2], o[f][nt][3],
                             p[f][1][0], p[f][1][1], p[f][1][2], p[f][1][3], b2, b3);
                }
            }
        }
        __syncthreads();
    }

    // ---- epilogue: reduce lr across the 4 qc lanes, then leaky(o/l) - x ----
    #pragma unroll
    for (int f = 0; f < 2; f++) {
        float l0 = lr[f][0], l1 = lr[f][1];
        l0 += __shfl_xor_sync(0xffffffffu, l0, 1);
        l0 += __shfl_xor_sync(0xffffffffu, l0, 2);
        l1 += __shfl_xor_sync(0xffffffffu, l1, 1);
        l1 += __shfl_xor_sync(0xffffffffu, l1, 2);
        float inv0 = 1.f / l0, inv1 = 1.f / l1;
        size_t gm0 = (size_t)(n*MM + rbase + f*16);
        size_t gm1 = gm0 + 8;
        const float* x0 = x + gm0*DD;
        const float* x1 = x + gm1*DD;
        float* d0 = g_dx + gm0*(HH*DD) + h*DD;
        float* d1 = g_dx + gm1*(HH*DD) + h*DD;
        #pragma unroll
        for (int nt = 0; nt < 8; nt++) {
            int cb = nt*8 + 2*qc;
            float2 xv0 = *(const float2*)&x0[cb];
            float2 xv1 = *(const float2*)&x1[cb];
            float v00 = o[f][nt][0]*inv0; v00 = (v00 > 0.f ? v00 : NEG*v00) - xv0.x;
            float v01 = o[f][nt][1]*inv0; v01 = (v01 > 0.f ? v01 : NEG*v01) - xv0.y;
            float v10 = o[f][nt][2]*inv1; v10 = (v10 > 0.f ? v10 : NEG*v10) - xv1.x;
            float v11 = o[f][nt][3]*inv1; v11 = (v11 > 0.f ? v11 : NEG*v11) - xv1.y;
            *(float2*)&d0[cb] = make_float2(v00, v01);
            *(float2*)&d1[cb] = make_float2(v10, v11);
        }
    }
}

// ---------------------------------------------------------------------------
// Kernel 3: decoder (fp32 SIMT, near its FMA floor).  (unchanged)
// ---------------------------------------------------------------------------
#define DEC_SMEM ((64*256 + 64*257) * 4)

__global__ __launch_bounds__(256) void dec_kernel(
    const float* __restrict__ Wdec, const float* __restrict__ bdec,
    float* __restrict__ out)
{
    extern __shared__ float sm[];
    float* ds = sm;
    float* Ws = ds + 64*256;
    int row0 = blockIdx.x * 64;
    int tx = threadIdx.x, ty = threadIdx.y;
    int tid = ty*16 + tx;
    #pragma unroll
    for (int r = 0; r < 64; r++) {
        int l = r*256 + tid;
        ds[l] = g_dx[(size_t)row0*256 + l];
        Ws[(l>>8)*257 + (l&255)] = Wdec[l];
    }
    __syncthreads();
    float acc[4][4] = {};
    int ty4 = ty*4;
    #pragma unroll 4
    for (int c = 0; c < 256; c += 4) {
        float4 dr[4];
        #pragma unroll
        for (int a = 0; a < 4; a++)
            dr[a] = *(const float4*)&ds[(ty4+a)*256 + c];
        #pragma unroll
        for (int b = 0; b < 4; b++) {
            const float* wp = &Ws[(b*16+tx)*257 + c];
            float w0 = wp[0], w1 = wp[1], w2 = wp[2], w3 = wp[3];
            #pragma unroll
            for (int a = 0; a < 4; a++) {
                acc[a][b] = fmaf(dr[a].x, w0, acc[a][b]);
                acc[a][b] = fmaf(dr[a].y, w1, acc[a][b]);
                acc[a][b] = fmaf(dr[a].z, w2, acc[a][b]);
                acc[a][b] = fmaf(dr[a].w, w3, acc[a][b]);
            }
        }
    }
    #pragma unroll
    for (int b = 0; b < 4; b++) {
        float bb = bdec[b*16 + tx];
        #pragma unroll
        for (int a = 0; a < 4; a++)
            out[(size_t)(row0 + ty4 + a)*DD + b*16 + tx] = acc[a][b] + bb;
    }
}

// ---------------------------------------------------------------------------
extern "C" void kernel_launch(void* const* d_in, const int* in_sizes, int n_in,
                              void* d_out, int out_size)
{
    const float* x    = (const float*)d_in[0];
    // d_in[1] = edge (unused)
    const float* Wk   = (const float*)d_in[2];
    const float* bk   = (const float*)d_in[3];
    const float* Wq   = (const float*)d_in[4];
    const float* bq   = (const float*)d_in[5];
    const float* Wv   = (const float*)d_in[6];
    const float* bv   = (const float*)d_in[7];
    const float* Wdec = (const float*)d_in[8];
    const float* bdec = (const float*)d_in[9];
    float* out = (float*)d_out;

    cudaFuncSetAttribute(attn_tc,    cudaFuncAttributeMaxDynamicSharedMemorySize, ATTN2_SMEM);
    cudaFuncSetAttribute(dec_kernel, cudaFuncAttributeMaxDynamicSharedMemorySize, DEC_SMEM);

    wprep<<<12, 256>>>(Wk, Wq, Wv);
    qkv_tc<<<dim3(MM/128, 3*HH, NB), 256>>>(x, bk, bq, bv);
    attn_tc<<<dim3(MM/128, HH, NB), 128, ATTN2_SMEM>>>(x);
    dec_kernel<<<NB*MM/64, dim3(16,16), DEC_SMEM>>>(Wdec, bdec, out);
}

// round 12
// speedup vs baseline: 1.9861x; 1.0679x over previous
#include <cuda_runtime.h>
#include <cuda_bf16.h>

#define NB 16
#define MM 1024
#define DD 64
#define HH 4
#define NEG 0.2f
#define ESHIFT 20.0f

// Scratch (allocation-free rule: __device__ globals)
__device__ float g_K[NB*HH*MM*DD];   // [n,h,m,d]   fp32
__device__ float g_Q[NB*HH*MM*DD];   // [n,h,m,d']  tf32-rounded, d-permuted
__device__ float g_V[NB*HH*MM*DD];   // Vt [n,h,e,m'] tf32-rounded, transposed + j-permuted
__device__ float g_dx[NB*MM*HH*DD];

// Conflict-free compact smem layout for attn tiles: 64-float row -> 4 blocks
// of 16 floats at offsets {0,20,40,60}, row stride 80 floats.
#define SSTR 80
#define TILEF (64*SSTR)          // 5120 floats = 20.5KB per 64x64 tile

// Packed bf16-split projection weights: per (which*HH+h): 64 e-rows x 40 words.
// Word p in row: chunk c (k/16) at c*8 + 2*(jj&3) + (jj>>2), jj=(k%16)/2.
// Thread (n=lane>>2, qc=lane&3) loads uint2 at row*40 + c*8 + 2*qc = {b0,b1}.
#define WSTR 40
#define WWORDS (64*WSTR)         // 2560 words per plane per head
__device__ unsigned g_Wbh[12*WWORDS];
__device__ unsigned g_Wbl[12*WWORDS];

__device__ __forceinline__ unsigned f2tf32(float f) {
    unsigned u;
    asm("cvt.rna.tf32.f32 %0, %1;" : "=r"(u) : "f"(f));
    return u;
}

__device__ __forceinline__ void mma_tf32(float& d0, float& d1, float& d2, float& d3,
                                         unsigned a0, unsigned a1, unsigned a2, unsigned a3,
                                         unsigned b0, unsigned b1) {
    asm volatile("mma.sync.aligned.m16n8k8.row.col.f32.tf32.tf32.f32 "
                 "{%0,%1,%2,%3}, {%4,%5,%6,%7}, {%8,%9}, {%0,%1,%2,%3};"
                 : "+f"(d0), "+f"(d1), "+f"(d2), "+f"(d3)
                 : "r"(a0), "r"(a1), "r"(a2), "r"(a3), "r"(b0), "r"(b1));
}

__device__ __forceinline__ void mma_bf16(float* d,
                                         unsigned a0, unsigned a1, unsigned a2, unsigned a3,
                                         unsigned b0, unsigned b1) {
    asm volatile("mma.sync.aligned.m16n8k16.row.col.f32.bf16.bf16.f32 "
                 "{%0,%1,%2,%3}, {%4,%5,%6,%7}, {%8,%9}, {%0,%1,%2,%3};"
                 : "+f"(d[0]), "+f"(d[1]), "+f"(d[2]), "+f"(d[3])
                 : "r"(a0), "r"(a1), "r"(a2), "r"(a3), "r"(b0), "r"(b1));
}

__device__ __forceinline__ void cp16(unsigned dst_smem, const void* src) {
    asm volatile("cp.async.cg.shared.global [%0], [%1], 16;" :: "r"(dst_smem), "l"(src));
}

// d-permutation (GMEM, for B-frag float4 packing): d' = (d%4)*16 + d/4
__device__ __forceinline__ int dperm(int d) { return (d & 3)*16 + (d >> 2); }
// j-permutation matching the S c-frag column order: j = 8k+2q+r -> q*16 + 2k + r
__device__ __forceinline__ int jperm(int j) {
    return ((j >> 1) & 3)*16 + ((j >> 3) << 1) + (j & 1);
}

// bf16 2-term split of a float2, packed low-first (element k in bits[15:0])
__device__ __forceinline__ void bsplit(float2 f, unsigned& hi, unsigned& lo) {
    __nv_bfloat162 h = __float22bfloat162_rn(f);
    float2 hf = __bfloat1622float2(h);
    __nv_bfloat162 l = __float22bfloat162_rn(make_float2(f.x - hf.x, f.y - hf.y));
    hi = *(unsigned*)&h;
    lo = *(unsigned*)&l;
}

// ---------------------------------------------------------------------------
// Kernel 0: weight prep — bf16 hi/lo split, packed + permuted for m16n8k16.
// grid 12, block 256. ~2-3 us.
// ---------------------------------------------------------------------------
__global__ __launch_bounds__(256) void wprep(
    const float* __restrict__ Wk,
    const float* __restrict__ Wq,
    const float* __restrict__ Wv)
{
    int bid = blockIdx.x;
    int which = bid / HH, h = bid % HH;
    const float* W = ((which == 0) ? Wk : (which == 1) ? Wq : Wv) + h*DD*DD;
    unsigned* oh = g_Wbh + (size_t)bid*WWORDS;
    unsigned* ol = g_Wbl + (size_t)bid*WWORDS;
    for (int l = threadIdx.x; l < 64*32; l += 256) {
        int e = l >> 5, j = l & 31;           // j = k/2
        float2 w = make_float2(W[e*64 + 2*j], W[e*64 + 2*j + 1]);
        unsigned hi, lo;
        bsplit(w, hi, lo);
        int c = j >> 3, jj = j & 7;
        int p = c*8 + 2*(jj & 3) + (jj >> 2);
        oh[e*WSTR + p] = hi;
        ol[e*WSTR + p] = lo;
    }
}

// ---------------------------------------------------------------------------
// Kernel 1: bf16-split tensor-core K/Q/V projections (m16n8k16, 3 products).
// grid (M/128, 3*H, N), block 256 (8 warps, 16 rows each).
// ---------------------------------------------------------------------------
__global__ __launch_bounds__(256, 2) void qkv_tc(
    const float* __restrict__ x,
    const float* __restrict__ bk,
    const float* __restrict__ bq,
    const float* __restrict__ bv)
{
    __shared__ unsigned Wh[WWORDS];
    __shared__ unsigned Wl[WWORDS];
    int n = blockIdx.z;
    int which = blockIdx.y / HH;
    int h = blockIdx.y % HH;
    int mtile = blockIdx.x * 128;
    const float* bias = (which == 0) ? bk : (which == 1) ? bq : bv;
    int tid = threadIdx.x;
    int warp = tid >> 5, lane = tid & 31;
    int qr = lane >> 2, qc = lane & 3;

    {
        unsigned swh = (unsigned)__cvta_generic_to_shared(Wh);
        unsigned swl = (unsigned)__cvta_generic_to_shared(Wl);
        const unsigned* srcH = g_Wbh + (size_t)blockIdx.y*WWORDS;
        const unsigned* srcL = g_Wbl + (size_t)blockIdx.y*WWORDS;
        #pragma unroll
        for (int r = 0; r < 5; r++) {
            int idx = r*256 + tid;            // 1280 float4-chunks total
            if (idx < 640) cp16(swh + idx*16, srcH + idx*4);
            else           cp16(swl + (idx-640)*16, srcL + (idx-640)*4);
        }
        asm volatile("cp.async.commit_group;");
    }

    int r0 = mtile + warp*16 + qr;
    const float* xg0 = x + (size_t)(n*MM + r0)*DD;
    const float* xg1 = xg0 + 8*DD;

    // A-frags: bf16 hi/lo for both rows, 4 k-chunks of 16
    unsigned ah[4][4], al[4][4];
    #pragma unroll
    for (int c = 0; c < 4; c++) {
        float2 f00 = *(const float2*)&xg0[16*c + 2*qc];
        float2 f10 = *(const float2*)&xg1[16*c + 2*qc];
        float2 f01 = *(const float2*)&xg0[16*c + 2*qc + 8];
        float2 f11 = *(const float2*)&xg1[16*c + 2*qc + 8];
        bsplit(f00, ah[c][0], al[c][0]);
        bsplit(f10, ah[c][1], al[c][1]);
        bsplit(f01, ah[c][2], al[c][2]);
        bsplit(f11, ah[c][3], al[c][3]);
    }

    asm volatile("cp.async.wait_group 0;");
    __syncthreads();

    float o[8][4] = {};
    #pragma unroll
    for (int nt = 0; nt < 8; nt++) {
        int base = (nt*8 + qr)*WSTR + 2*qc;
        #pragma unroll
        for (int c = 0; c < 4; c++) {
            uint2 bh = *(const uint2*)&Wh[base + c*8];
            uint2 bl = *(const uint2*)&Wl[base + c*8];
            mma_bf16(o[nt], ah[c][0], ah[c][1], ah[c][2], ah[c][3], bh.x, bh.y);
            mma_bf16(o[nt], ah[c][0], ah[c][1], ah[c][2], ah[c][3], bl.x, bl.y);
            mma_bf16(o[nt], al[c][0], al[c][1], al[c][2], al[c][3], bh.x, bh.y);
        }
    }

    // epilogue (layouts unchanged)
    size_t hb = (size_t)(n*HH + h);
    if (which == 0) {
        float* Ko = g_K + hb*MM*DD;
        #pragma unroll
        for (int nt = 0; nt < 8; nt++) {
            int c0 = nt*8 + 2*qc;
            float b0 = bias[h*DD + c0], b1 = bias[h*DD + c0 + 1];
            *(float2*)&Ko[(size_t)r0*DD + c0]     = make_float2(o[nt][0]+b0, o[nt][1]+b1);
            *(float2*)&Ko[(size_t)(r0+8)*DD + c0] = make_float2(o[nt][2]+b0, o[nt][3]+b1);
        }
    } else if (which == 1) {
        float* Qo = g_Q + hb*MM*DD;
        #pragma unroll
        for (int nt = 0; nt < 8; nt++) {
            int c0 = nt*8 + 2*qc;
            float b0 = bias[h*DD + c0], b1 = bias[h*DD + c0 + 1];
            int dp = dperm(c0);
            Qo[(size_t)r0*DD + dp]          = __uint_as_float(f2tf32(o[nt][0]+b0));
            Qo[(size_t)r0*DD + dp + 16]     = __uint_as_float(f2tf32(o[nt][1]+b1));
            Qo[(size_t)(r0+8)*DD + dp]      = __uint_as_float(f2tf32(o[nt][2]+b0));
            Qo[(size_t)(r0+8)*DD + dp + 16] = __uint_as_float(f2tf32(o[nt][3]+b1));
        }
    } else {
        float* Vt = g_V + hb*DD*MM;   // [e][m']
        int mp0 = (r0 & ~63) + jperm(r0 & 63);
        int mp1 = ((r0+8) & ~63) + jperm((r0+8) & 63);
        #pragma unroll
        for (int nt = 0; nt < 8; nt++) {
            int c0 = nt*8 + 2*qc;
            float b0 = bias[h*DD + c0], b1 = bias[h*DD + c0 + 1];
            Vt[(size_t)c0*MM     + mp0] = __uint_as_float(f2tf32(o[nt][0]+b0));
            Vt[(size_t)(c0+1)*MM + mp0] = __uint_as_float(f2tf32(o[nt][1]+b1));
            Vt[(size_t)c0*MM     + mp1] = __uint_as_float(f2tf32(o[nt][2]+b0));
            Vt[(size_t)(c0+1)*MM + mp1] = __uint_as_float(f2tf32(o[nt][3]+b1));
        }
    }
}

// ---------------------------------------------------------------------------
// Kernel 2: TF32 flash attention (unchanged from R11 best).
// ---------------------------------------------------------------------------
#define ATTN2_SMEM (4*TILEF*4)    // 81.9 KB -> 2 CTAs/SM

__global__ __launch_bounds__(128, 2) void attn_tc(const float* __restrict__ x)
{
    extern __shared__ float sm[];

    int n = blockIdx.z, h = blockIdx.y;
    int itile = blockIdx.x * 128;
    int tid = threadIdx.x;
    int warp = tid >> 5, lane = tid & 31;
    int qr = lane >> 2, qc = lane & 3;

    const float* Kg = g_K + (size_t)(n*HH + h)*MM*DD;
    const float* Qb = g_Q + (size_t)(n*HH + h)*MM*DD;
    const float* Vb = g_V + (size_t)(n*HH + h)*DD*MM;   // Vt [e][m']

    int rbase = itile + warp*32 + qr;

    unsigned ka[2][8][4];
    #pragma unroll
    for (int f = 0; f < 2; f++) {
        int r0 = rbase + f*16;
        #pragma unroll
        for (int kk = 0; kk < 8; kk++) {
            ka[f][kk][0] = f2tf32(Kg[(size_t)r0*DD     + kk*8 + qc    ]);
            ka[f][kk][1] = f2tf32(Kg[(size_t)(r0+8)*DD + kk*8 + qc    ]);
            ka[f][kk][2] = f2tf32(Kg[(size_t)r0*DD     + kk*8 + qc + 4]);
            ka[f][kk][3] = f2tf32(Kg[(size_t)(r0+8)*DD + kk*8 + qc + 4]);
        }
    }

    float o[2][8][4] = {};
    float lr[2][2] = {};

    unsigned base0 = (unsigned)__cvta_generic_to_shared(sm);
    unsigned qbase[2] = { base0, base0 + TILEF*4 };
    unsigned vbase[2] = { base0 + 2*TILEF*4, base0 + 3*TILEF*4 };

    int sg_q  = lane & 3;
    int sg_rb = (lane >> 2) & 1;
    int sg_k  = lane >> 3;
    int sg_col = sg_q*16 + sg_k*4;
    int sg_ofs = (sg_q*20 + sg_k*4)*4;

    #pragma unroll
    for (int rnd = 0; rnd < 8; rnd++) {
        int row = rnd*8 + 2*warp + sg_rb;
        unsigned so = row*SSTR*4 + sg_ofs;
        cp16(qbase[0] + so, Qb + (size_t)row*DD + sg_col);
        cp16(vbase[0] + so, Vb + (size_t)row*MM + sg_col);
    }
    asm volatile("cp.async.commit_group;");

    for (int jt = 0; jt < 16; jt++) {
        int buf = jt & 1;
        if (jt < 15) {
            int nb = buf ^ 1;
            const float* qg = Qb + (size_t)(jt+1)*64*DD;
            const float* vg = Vb + (jt+1)*64;
            #pragma unroll
            for (int rnd = 0; rnd < 8; rnd++) {
                int row = rnd*8 + 2*warp + sg_rb;
                unsigned so = row*SSTR*4 + sg_ofs;
                cp16(qbase[nb] + so, qg + (size_t)row*DD + sg_col);
                cp16(vbase[nb] + so, vg + (size_t)row*MM + sg_col);
            }
            asm volatile("cp.async.commit_group;");
            asm volatile("cp.async.wait_group 1;");
        } else {
            asm volatile("cp.async.wait_group 0;");
        }
        __syncthreads();

        const float* Qc = sm + buf*TILEF;
        const float* Vc = sm + (2+buf)*TILEF;

        float s[2][8][4];
        #pragma unroll
        for (int nt = 0; nt < 8; nt++) {
            s[0][nt][0] = s[0][nt][1] = s[0][nt][2] = s[0][nt][3] = 0.f;
            s[1][nt][0] = s[1][nt][1] = s[1][nt][2] = s[1][nt][3] = 0.f;
            const float* qrow = &Qc[(nt*8 + qr)*SSTR + qc*20];
            #pragma unroll
            for (int kkp = 0; kkp < 4; kkp++) {
                float4 g = *(const float4*)&qrow[4*kkp];
                unsigned b0 = __float_as_uint(g.x), b1 = __float_as_uint(g.y);
                unsigned b2 = __float_as_uint(g.z), b3 = __float_as_uint(g.w);
                #pragma unroll
                for (int f = 0; f < 2; f++) {
                    mma_tf32(s[f][nt][0], s[f][nt][1], s[f][nt][2], s[f][nt][3],
                             ka[f][2*kkp][0], ka[f][2*kkp][1], ka[f][2*kkp][2], ka[f][2*kkp][3],
                             b0, b1);
                    mma_tf32(s[f][nt][0], s[f][nt][1], s[f][nt][2], s[f][nt][3],
                             ka[f][2*kkp+1][0], ka[f][2*kkp+1][1], ka[f][2*kkp+1][2], ka[f][2*kkp+1][3],
                             b2, b3);
                }
            }
        }

        #pragma unroll
        for (int f = 0; f < 2; f++) {
            #pragma unroll
            for (int nt = 0; nt < 8; nt++) {
                #pragma unroll
                for (int c = 0; c < 4; c++) {
                    float sv = s[f][nt][c];
                    sv = sv > 0.f ? sv : NEG*sv;
                    s[f][nt][c] = __expf(sv - ESHIFT);
                }
                lr[f][0] += s[f][nt][0] + s[f][nt][1];
                lr[f][1] += s[f][nt][2] + s[f][nt][3];
            }
        }

        #pragma unroll
        for (int kkp = 0; kkp < 4; kkp++) {
            int k0 = 2*kkp, k1 = 2*kkp + 1;
            unsigned p[2][2][4];
            #pragma unroll
            for (int f = 0; f < 2; f++) {
                p[f][0][0] = f2tf32(s[f][k0][0]); p[f][0][1] = f2tf32(s[f][k0][2]);
                p[f][0][2] = f2tf32(s[f][k0][1]); p[f][0][3] = f2tf32(s[f][k0][3]);
                p[f][1][0] = f2tf32(s[f][k1][0]); p[f][1][1] = f2tf32(s[f][k1][2]);
                p[f][1][2] = f2tf32(s[f][k1][1]); p[f][1][3] = f2tf32(s[f][k1][3]);
            }
            #pragma unroll
            for (int nt = 0; nt < 8; nt++) {
                float4 g = *(const float4*)&Vc[(nt*8 + qr)*SSTR + qc*20 + 4*kkp];
                unsigned b0 = __float_as_uint(g.x), b1 = __float_as_uint(g.y);
                unsigned b2 = __float_as_uint(g.z), b3 = __float_as_uint(g.w);
                #pragma unroll
                for (int f = 0; f < 2; f++) {
                    mma_tf32(o[f][nt][0], o[f][nt][1], o[f][nt][2], o[f][nt][3],
                             p[f][0][0], p[f][0][1], p[f][0][2], p[f][0][3], b0, b1);
                    mma_tf32(o[f][nt][0], o[f][nt][1], o[f][nt][2], o[f][nt][3],
                             p[f][1][0], p[f][1][1], p[f][1][2], p[f][1][3], b2, b3);
                }
            }
        }
        __syncthreads();
    }

    #pragma unroll
    for (int f = 0; f < 2; f++) {
        float l0 = lr[f][0], l1 = lr[f][1];
        l0 += __shfl_xor_sync(0xffffffffu, l0, 1);
        l0 += __shfl_xor_sync(0xffffffffu, l0, 2);
        l1 += __shfl_xor_sync(0xffffffffu, l1, 1);
        l1 += __shfl_xor_sync(0xffffffffu, l1, 2);
        float inv0 = 1.f / l0, inv1 = 1.f / l1;
        size_t gm0 = (size_t)(n*MM + rbase + f*16);
        size_t gm1 = gm0 + 8;
        const float* x0 = x + gm0*DD;
        const float* x1 = x + gm1*DD;
        float* d0 = g_dx + gm0*(HH*DD) + h*DD;
        float* d1 = g_dx + gm1*(HH*DD) + h*DD;
        #pragma unroll
        for (int nt = 0; nt < 8; nt++) {
            int cb = nt*8 + 2*qc;
            float2 xv0 = *(const float2*)&x0[cb];
            float2 xv1 = *(const float2*)&x1[cb];
            float v00 = o[f][nt][0]*inv0; v00 = (v00 > 0.f ? v00 : NEG*v00) - xv0.x;
            float v01 = o[f][nt][1]*inv0; v01 = (v01 > 0.f ? v01 : NEG*v01) - xv0.y;
            float v10 = o[f][nt][2]*inv1; v10 = (v10 > 0.f ? v10 : NEG*v10) - xv1.x;
            float v11 = o[f][nt][3]*inv1; v11 = (v11 > 0.f ? v11 : NEG*v11) - xv1.y;
            *(float2*)&d0[cb] = make_float2(v00, v01);
            *(float2*)&d1[cb] = make_float2(v10, v11);
        }
    }
}

// ---------------------------------------------------------------------------
// Kernel 3: decoder, 32 rows/CTA (grid 512) -> 97KB smem -> 2 CTAs/SM.
// cp.async prologue; Ws stride 260 (16B-aligned rows, conflict-free reads).
// ---------------------------------------------------------------------------
#define WDSTR 260
#define DEC_SMEM ((32*256 + 64*WDSTR) * 4)   // 99328 B

__global__ __launch_bounds__(256, 2) void dec_kernel(
    const float* __restrict__ Wdec, const float* __restrict__ bdec,
    float* __restrict__ out)
{
    extern __shared__ float sm[];
    float* ds = sm;                 // [32][256]
    float* Ws = ds + 32*256;        // [64][260]
    int row0 = blockIdx.x * 32;
    int tx = threadIdx.x, ty = threadIdx.y;
    int tid = ty*16 + tx;

    {
        unsigned sds = (unsigned)__cvta_generic_to_shared(ds);
        unsigned sws = (unsigned)__cvta_generic_to_shared(Ws);
        const float* dsrc = g_dx + (size_t)row0*256;
        #pragma unroll
        for (int r = 0; r < 8; r++) {       // 2048 float4: dx tile (contiguous)
            int idx = r*256 + tid;
            cp16(sds + idx*16, dsrc + idx*4);
        }
        #pragma unroll
        for (int r = 0; r < 16; r++) {      // 4096 float4: Wdec (re-strided)
            int idx = r*256 + tid;
            int wrow = idx >> 6, c4 = idx & 63;
            cp16(sws + (wrow*WDSTR + c4*4)*4, Wdec + wrow*256 + c4*4);
        }
        asm volatile("cp.async.commit_group;");
        asm volatile("cp.async.wait_group 0;");
    }
    __syncthreads();

    float acc[2][4] = {};
    int ty2 = ty*2;
    #pragma unroll 4
    for (int c = 0; c < 256; c += 4) {
        float4 dr[2];
        #pragma unroll
        for (int a = 0; a < 2; a++)
            dr[a] = *(const float4*)&ds[(ty2+a)*256 + c];
        #pragma unroll
        for (int b = 0; b < 4; b++) {
            const float* wp = &Ws[(b*16+tx)*WDSTR + c];
            float w0 = wp[0], w1 = wp[1], w2 = wp[2], w3 = wp[3];
            #pragma unroll
            for (int a = 0; a < 2; a++) {
                acc[a][b] = fmaf(dr[a].x, w0, acc[a][b]);
                acc[a][b] = fmaf(dr[a].y, w1, acc[a][b]);
                acc[a][b] = fmaf(dr[a].z, w2, acc[a][b]);
                acc[a][b] = fmaf(dr[a].w, w3, acc[a][b]);
            }
        }
    }
    #pragma unroll
    for (int b = 0; b < 4; b++) {
        float bb = bdec[b*16 + tx];
        #pragma unroll
        for (int a = 0; a < 2; a++)
            out[(size_t)(row0 + ty2 + a)*DD + b*16 + tx] = acc[a][b] + bb;
    }
}

// ---------------------------------------------------------------------------
extern "C" void kernel_launch(void* const* d_in, const int* in_sizes, int n_in,
                              void* d_out, int out_size)
{
    const float* x    = (const float*)d_in[0];
    // d_in[1] = edge (unused)
    const float* Wk   = (const float*)d_in[2];
    const float* bk   = (const float*)d_in[3];
    const float* Wq   = (const float*)d_in[4];
    const float* bq   = (const float*)d_in[5];
    const float* Wv   = (const float*)d_in[6];
    const float* bv   = (const float*)d_in[7];
    const float* Wdec = (const float*)d_in[8];
    const float* bdec = (const float*)d_in[9];
    float* out = (float*)d_out;

    cudaFuncSetAttribute(attn_tc,    cudaFuncAttributeMaxDynamicSharedMemorySize, ATTN2_SMEM);
    cudaFuncSetAttribute(dec_kernel, cudaFuncAttributeMaxDynamicSharedMemorySize, DEC_SMEM);

    wprep<<<12, 256>>>(Wk, Wq, Wv);
    qkv_tc<<<dim3(MM/128, 3*HH, NB), 256>>>(x, bk, bq, bv);
    attn_tc<<<dim3(MM/128, HH, NB), 128, ATTN2_SMEM>>>(x);
    dec_kernel<<<NB*MM/32, dim3(16,16), DEC_SMEM>>>(Wdec, bdec, out);
}

// round 15
// speedup vs baseline: 2.8745x; 1.4473x over previous
#include <cuda_runtime.h>
#include <cuda_bf16.h>
#include <cuda_fp16.h>

#define NB 16
#define MM 1024
#define DD 64
#define HH 4
#define NEG 0.2f

// ---------------- device scratch (allocation-free rule) ----------------
__device__ float g_dx[NB*MM*HH*DD];

// fp16 packed planes from qkv: K,Q as [n,h,m, 32 words] (word w = elems 2w,2w+1
// of d); V transposed-packed: [n,h,e, 512 words] (word w = Vt[e][2w],Vt[e][2w+1]).
__device__ unsigned g_Kp[NB*HH*MM*32];
__device__ unsigned g_Qp[NB*HH*MM*32];
__device__ unsigned g_Vp[NB*HH*DD*(MM/2)];

// Packed bf16-split projection weights (wprep output), per (which*HH+h)
#define WSTR 40
#define WWORDS (64*WSTR)
__device__ unsigned g_Wbh[12*WWORDS];
__device__ unsigned g_Wbl[12*WWORDS];

// ---------------- helpers ----------------
__device__ __forceinline__ void mma_bf16(float* d,
                                         unsigned a0, unsigned a1, unsigned a2, unsigned a3,
                                         unsigned b0, unsigned b1) {
    asm volatile("mma.sync.aligned.m16n8k16.row.col.f32.bf16.bf16.f32 "
                 "{%0,%1,%2,%3}, {%4,%5,%6,%7}, {%8,%9}, {%0,%1,%2,%3};"
                 : "+f"(d[0]), "+f"(d[1]), "+f"(d[2]), "+f"(d[3])
                 : "r"(a0), "r"(a1), "r"(a2), "r"(a3), "r"(b0), "r"(b1));
}

__device__ __forceinline__ void mma_fp16(float* d,
                                         unsigned a0, unsigned a1, unsigned a2, unsigned a3,
                                         unsigned b0, unsigned b1) {
    asm volatile("mma.sync.aligned.m16n8k16.row.col.f32.f16.f16.f32 "
                 "{%0,%1,%2,%3}, {%4,%5,%6,%7}, {%8,%9}, {%0,%1,%2,%3};"
                 : "+f"(d[0]), "+f"(d[1]), "+f"(d[2]), "+f"(d[3])
                 : "r"(a0), "r"(a1), "r"(a2), "r"(a3), "r"(b0), "r"(b1));
}

__device__ __forceinline__ void cp16(unsigned dst_smem, const void* src) {
    asm volatile("cp.async.cg.shared.global [%0], [%1], 16;" :: "r"(dst_smem), "l"(src));
}

__device__ __forceinline__ void bsplit(float2 f, unsigned& hi, unsigned& lo) {
    __nv_bfloat162 h = __float22bfloat162_rn(f);
    float2 hf = __bfloat1622float2(h);
    __nv_bfloat162 l = __float22bfloat162_rn(make_float2(f.x - hf.x, f.y - hf.y));
    hi = *(unsigned*)&h;
    lo = *(unsigned*)&l;
}

__device__ __forceinline__ unsigned pack_h2(float a, float b) {
    __half2 h = __float22half2_rn(make_float2(a, b));   // a in low half
    return *(unsigned*)&h;
}

// ---------------------------------------------------------------------------
// Kernel 0: weight prep (unchanged from R12)
// ---------------------------------------------------------------------------
__global__ __launch_bounds__(256) void wprep(
    const float* __restrict__ Wk,
    const float* __restrict__ Wq,
    const float* __restrict__ Wv)
{
    int bid = blockIdx.x;
    int which = bid / HH, h = bid % HH;
    const float* W = ((which == 0) ? Wk : (which == 1) ? Wq : Wv) + h*DD*DD;
    unsigned* oh = g_Wbh + (size_t)bid*WWORDS;
    unsigned* ol = g_Wbl + (size_t)bid*WWORDS;
    for (int l = threadIdx.x; l < 64*32; l += 256) {
        int e = l >> 5, j = l & 31;
        float2 w = make_float2(W[e*64 + 2*j], W[e*64 + 2*j + 1]);
        unsigned hi, lo;
        bsplit(w, hi, lo);
        int c = j >> 3, jj = j & 7;
        int p = c*8 + 2*(jj & 3) + (jj >> 2);
        oh[e*WSTR + p] = hi;
        ol[e*WSTR + p] = lo;
    }
}

// ---------------------------------------------------------------------------
// Kernel 1: bf16-split projections (mma identical to R12); epilogue writes
// fp16 packed planes: K,Q [m][32 words]; V transposed-packed [e][m/2 words]
// (pairs over m formed via shfl_down(4) row exchange).
// ---------------------------------------------------------------------------
__global__ __launch_bounds__(256, 2) void qkv_tc(
    const float* __restrict__ x,
    const float* __restrict__ bk,
    const float* __restrict__ bq,
    const float* __restrict__ bv)
{
    __shared__ unsigned Wh[WWORDS];
    __shared__ unsigned Wl[WWORDS];
    int n = blockIdx.z;
    int which = blockIdx.y / HH;
    int h = blockIdx.y % HH;
    int mtile = blockIdx.x * 128;
    const float* bias = (which == 0) ? bk : (which == 1) ? bq : bv;
    int tid = threadIdx.x;
    int warp = tid >> 5, lane = tid & 31;
    int qr = lane >> 2, qc = lane & 3;

    {
        unsigned swh = (unsigned)__cvta_generic_to_shared(Wh);
        unsigned swl = (unsigned)__cvta_generic_to_shared(Wl);
        const unsigned* srcH = g_Wbh + (size_t)blockIdx.y*WWORDS;
        const unsigned* srcL = g_Wbl + (size_t)blockIdx.y*WWORDS;
        #pragma unroll
        for (int r = 0; r < 5; r++) {
            int idx = r*256 + tid;
            if (idx < 640) cp16(swh + idx*16, srcH + idx*4);
            else           cp16(swl + (idx-640)*16, srcL + (idx-640)*4);
        }
        asm volatile("cp.async.commit_group;");
    }

    int r0 = mtile + warp*16 + qr;
    const float* xg0 = x + (size_t)(n*MM + r0)*DD;
    const float* xg1 = xg0 + 8*DD;

    unsigned ah[4][4], al[4][4];
    #pragma unroll
    for (int c = 0; c < 4; c++) {
        float2 f00 = *(const float2*)&xg0[16*c + 2*qc];
        float2 f10 = *(const float2*)&xg1[16*c + 2*qc];
        float2 f01 = *(const float2*)&xg0[16*c + 2*qc + 8];
        float2 f11 = *(const float2*)&xg1[16*c + 2*qc + 8];
        bsplit(f00, ah[c][0], al[c][0]);
        bsplit(f10, ah[c][1], al[c][1]);
        bsplit(f01, ah[c][2], al[c][2]);
        bsplit(f11, ah[c][3], al[c][3]);
    }

    asm volatile("cp.async.wait_group 0;");
    __syncthreads();

    float o[8][4] = {};
    #pragma unroll
    for (int nt = 0; nt < 8; nt++) {
        int base = (nt*8 + qr)*WSTR + 2*qc;
        #pragma unroll
        for (int c = 0; c < 4; c++) {
            uint2 bh = *(const uint2*)&Wh[base + c*8];
            uint2 bl = *(const uint2*)&Wl[base + c*8];
            mma_bf16(o[nt], ah[c][0], ah[c][1], ah[c][2], ah[c][3], bh.x, bh.y);
            mma_bf16(o[nt], ah[c][0], ah[c][1], ah[c][2], ah[c][3], bl.x, bl.y);
            mma_bf16(o[nt], al[c][0], al[c][1], al[c][2], al[c][3], bh.x, bh.y);
        }
    }

    size_t hb = (size_t)(n*HH + h);
    if (which != 2) {
        unsigned* Pp = (which == 0 ? g_Kp : g_Qp) + hb*MM*32;
        #pragma unroll
        for (int nt = 0; nt < 8; nt++) {
            int c0 = nt*8 + 2*qc;
            float b0 = bias[h*DD + c0], b1 = bias[h*DD + c0 + 1];
            int w = 4*nt + qc;                          // word = c0/2
            Pp[(size_t)r0*32 + w]     = pack_h2(o[nt][0]+b0, o[nt][1]+b1);
            Pp[(size_t)(r0+8)*32 + w] = pack_h2(o[nt][2]+b0, o[nt][3]+b1);
        }
    } else {
        unsigned* Vp = g_Vp + hb*DD*(MM/2);
        #pragma unroll
        for (int nt = 0; nt < 8; nt++) {
            int c0 = nt*8 + 2*qc;
            float b0 = bias[h*DD + c0], b1 = bias[h*DD + c0 + 1];
            float v0 = o[nt][0]+b0, v1 = o[nt][1]+b1;
            float v2 = o[nt][2]+b0, v3 = o[nt][3]+b1;
            float p0 = __shfl_down_sync(0xffffffffu, v0, 4);
            float p1 = __shfl_down_sync(0xffffffffu, v1, 4);
            float p2 = __shfl_down_sync(0xffffffffu, v2, 4);
            float p3 = __shfl_down_sync(0xffffffffu, v3, 4);
            if (!(qr & 1)) {
                int w0 = r0 >> 1, w1 = (r0 + 8) >> 1;
                Vp[(size_t)c0*(MM/2)     + w0] = pack_h2(v0, p0);
                Vp[(size_t)(c0+1)*(MM/2) + w0] = pack_h2(v1, p1);
                Vp[(size_t)c0*(MM/2)     + w1] = pack_h2(v2, p2);
                Vp[(size_t)(c0+1)*(MM/2) + w1] = pack_h2(v3, p3);
            }
        }
    }
}

// ---------------------------------------------------------------------------
// Kernel 2: fp16 flash attention (m16n8k16, online softmax).
// 4 warps x 32 rows; smem row stride 36 words -> conflict-free scalar LDS
// (bank = 4*qr + qc + const). grid (M/128, H, N), block 128.
// ---------------------------------------------------------------------------
#define TSW 36                        // smem row stride in words

__global__ __launch_bounds__(128, 2) void attn_tc(const float* __restrict__ x)
{
    __shared__ unsigned QS[2][64*TSW];
    __shared__ unsigned VS[2][64*TSW];

    int n = blockIdx.z, h = blockIdx.y;
    int itile = blockIdx.x * 128;
    int tid = threadIdx.x;
    int warp = tid >> 5, lane = tid & 31;
    int qr = lane >> 2, qc = lane & 3;
    size_t hb = (size_t)(n*HH + h);

    const unsigned* Kp = g_Kp + hb*MM*32;
    const unsigned* Qp = g_Qp + hb*MM*32;
    const unsigned* Vp = g_Vp + hb*DD*(MM/2);

    int rbase = itile + warp*32 + qr;

    // Hoist K A-fragments (fp16 packed) for both i-frags
    unsigned ka[2][4][4];
    #pragma unroll
    for (int f = 0; f < 2; f++) {
        int r0 = rbase + f*16;
        #pragma unroll
        for (int c = 0; c < 4; c++) {
            ka[f][c][0] = Kp[(size_t)r0*32     + 8*c + qc];
            ka[f][c][1] = Kp[(size_t)(r0+8)*32 + 8*c + qc];
            ka[f][c][2] = Kp[(size_t)r0*32     + 8*c + 4 + qc];
            ka[f][c][3] = Kp[(size_t)(r0+8)*32 + 8*c + 4 + qc];
        }
    }

    float o[2][8][4] = {};
    float mr[2][2], lr[2][2];
    #pragma unroll
    for (int f = 0; f < 2; f++) { mr[f][0] = mr[f][1] = -1e30f; lr[f][0] = lr[f][1] = 0.f; }

    unsigned qb[2], vb[2];
    qb[0] = (unsigned)__cvta_generic_to_shared(QS[0]);
    qb[1] = (unsigned)__cvta_generic_to_shared(QS[1]);
    vb[0] = (unsigned)__cvta_generic_to_shared(VS[0]);
    vb[1] = (unsigned)__cvta_generic_to_shared(VS[1]);

    // staging: idx over 512 16B-chunks; row = idx>>3, c4 = idx&7
    // stage tile 0
    #pragma unroll
    for (int i = 0; i < 4; i++) {
        int idx = i*128 + tid;
        int row = idx >> 3, c4 = idx & 7;
        unsigned dofs = (row*TSW + c4*4)*4;
        cp16(qb[0] + dofs, Qp + (size_t)row*32 + c4*4);
        cp16(vb[0] + dofs, Vp + (size_t)row*(MM/2) + c4*4);
    }
    asm volatile("cp.async.commit_group;");

    for (int jt = 0; jt < 16; jt++) {
        int buf = jt & 1;
        if (jt < 15) {
            int nb = buf ^ 1;
            const unsigned* qg = Qp + (size_t)(jt+1)*64*32;
            const unsigned* vg = Vp + (jt+1)*32;
            #pragma unroll
            for (int i = 0; i < 4; i++) {
                int idx = i*128 + tid;
                int row = idx >> 3, c4 = idx & 7;
                unsigned dofs = (row*TSW + c4*4)*4;
                cp16(qb[nb] + dofs, qg + (size_t)row*32 + c4*4);
                cp16(vb[nb] + dofs, vg + (size_t)row*(MM/2) + c4*4);
            }
            asm volatile("cp.async.commit_group;");
            asm volatile("cp.async.wait_group 1;");
        } else {
            asm volatile("cp.async.wait_group 0;");
        }
        __syncthreads();

        const unsigned* Qc = QS[buf];
        const unsigned* Vc = VS[buf];

        // ---- S = K . Q^T (fp16 k16; 4 chunks cover k=64) ----
        float s[2][8][4];
        #pragma unroll
        for (int nt = 0; nt < 8; nt++) {
            s[0][nt][0] = s[0][nt][1] = s[0][nt][2] = s[0][nt][3] = 0.f;
            s[1][nt][0] = s[1][nt][1] = s[1][nt][2] = s[1][nt][3] = 0.f;
            const unsigned* qrow = &Qc[(nt*8 + qr)*TSW];
            #pragma unroll
            for (int c = 0; c < 4; c++) {
                unsigned b0 = qrow[8*c + qc];
                unsigned b1 = qrow[8*c + 4 + qc];
                #pragma unroll
                for (int f = 0; f < 2; f++)
                    mma_fp16(s[f][nt], ka[f][c][0], ka[f][c][1], ka[f][c][2], ka[f][c][3], b0, b1);
            }
        }

        // ---- leaky relu + online softmax (per i-frag) ----
        #pragma unroll
        for (int f = 0; f < 2; f++) {
            float m0 = -1e30f, m1 = -1e30f;
            #pragma unroll
            for (int nt = 0; nt < 8; nt++) {
                #pragma unroll
                for (int c = 0; c < 4; c++)
                    s[f][nt][c] = s[f][nt][c] > 0.f ? s[f][nt][c] : NEG*s[f][nt][c];
                m0 = fmaxf(m0, fmaxf(s[f][nt][0], s[f][nt][1]));
                m1 = fmaxf(m1, fmaxf(s[f][nt][2], s[f][nt][3]));
            }
            m0 = fmaxf(m0, __shfl_xor_sync(0xffffffffu, m0, 1));
            m0 = fmaxf(m0, __shfl_xor_sync(0xffffffffu, m0, 2));
            m1 = fmaxf(m1, __shfl_xor_sync(0xffffffffu, m1, 1));
            m1 = fmaxf(m1, __shfl_xor_sync(0xffffffffu, m1, 2));
            float nm0 = fmaxf(mr[f][0], m0), nm1 = fmaxf(mr[f][1], m1);
            float c0 = __expf(mr[f][0] - nm0), c1 = __expf(mr[f][1] - nm1);
            mr[f][0] = nm0; mr[f][1] = nm1;
            float a0 = 0.f, a1 = 0.f;
            #pragma unroll
            for (int nt = 0; nt < 8; nt++) {
                s[f][nt][0] = __expf(s[f][nt][0] - nm0);
                s[f][nt][1] = __expf(s[f][nt][1] - nm0);
                s[f][nt][2] = __expf(s[f][nt][2] - nm1);
                s[f][nt][3] = __expf(s[f][nt][3] - nm1);
                a0 += s[f][nt][0] + s[f][nt][1];
                a1 += s[f][nt][2] + s[f][nt][3];
                o[f][nt][0] *= c0; o[f][nt][1] *= c0; o[f][nt][2] *= c1; o[f][nt][3] *= c1;
            }
            a0 += __shfl_xor_sync(0xffffffffu, a0, 1);
            a0 += __shfl_xor_sync(0xffffffffu, a0, 2);
            a1 += __shfl_xor_sync(0xffffffffu, a1, 1);
            a1 += __shfl_xor_sync(0xffffffffu, a1, 2);
            lr[f][0] = lr[f][0]*c0 + a0;
            lr[f][1] = lr[f][1]*c1 + a1;
        }

        // ---- O += P . V (fp16; P A-frags packed from s registers) ----
        #pragma unroll
        for (int c = 0; c < 4; c++) {
            unsigned pa[2][4];
            #pragma unroll
            for (int f = 0; f < 2; f++) {
                pa[f][0] = pack_h2(s[f][2*c][0],   s[f][2*c][1]);
                pa[f][1] = pack_h2(s[f][2*c][2],   s[f][2*c][3]);
                pa[f][2] = pack_h2(s[f][2*c+1][0], s[f][2*c+1][1]);
                pa[f][3] = pack_h2(s[f][2*c+1][2], s[f][2*c+1][3]);
            }
            #pragma unroll
            for (int nt = 0; nt < 8; nt++) {
                const unsigned* vrow = &Vc[(nt*8 + qr)*TSW];
                unsigned b0 = vrow[8*c + qc];
                unsigned b1 = vrow[8*c + 4 + qc];
                #pragma unroll
                for (int f = 0; f < 2; f++)
                    mma_fp16(o[f][nt], pa[f][0], pa[f][1], pa[f][2], pa[f][3], b0, b1);
            }
        }
        __syncthreads();
    }

    // ---- epilogue: leaky(o/l) - x -> g_dx (N, M, H*D) ----
    #pragma unroll
    for (int f = 0; f < 2; f++) {
        float inv0 = 1.f / lr[f][0], inv1 = 1.f / lr[f][1];
        size_t gm0 = (size_t)(n*MM + rbase + f*16);
        size_t gm1 = gm0 + 8;
        const float* x0 = x + gm0*DD;
        const float* x1 = x + gm1*DD;
        float* d0 = g_dx + gm0*(HH*DD) + h*DD;
        float* d1 = g_dx + gm1*(HH*DD) + h*DD;
        #pragma unroll
        for (int nt = 0; nt < 8; nt++) {
            int cb = nt*8 + 2*qc;
            float2 xv0 = *(const float2*)&x0[cb];
            float2 xv1 = *(const float2*)&x1[cb];
            float v00 = o[f][nt][0]*inv0; v00 = (v00 > 0.f ? v00 : NEG*v00) - xv0.x;
            float v01 = o[f][nt][1]*inv0; v01 = (v01 > 0.f ? v01 : NEG*v01) - xv0.y;
            float v10 = o[f][nt][2]*inv1; v10 = (v10 > 0.f ? v10 : NEG*v10) - xv1.x;
            float v11 = o[f][nt][3]*inv1; v11 = (v11 > 0.f ? v11 : NEG*v11) - xv1.y;
            *(float2*)&d0[cb] = make_float2(v00, v01);
            *(float2*)&d1[cb] = make_float2(v10, v11);
        }
    }
}

// ---------------------------------------------------------------------------
// Kernel 3: decoder (unchanged from R12)
// ---------------------------------------------------------------------------
#define WDSTR 260
#define DEC_SMEM ((32*256 + 64*WDSTR) * 4)

__global__ __launch_bounds__(256, 2) void dec_kernel(
    const float* __restrict__ Wdec, const float* __restrict__ bdec,
    float* __restrict__ out)
{
    extern __shared__ float sm[];
    float* ds = sm;
    float* Ws = ds + 32*256;
    int row0 = blockIdx.x * 32;
    int tx = threadIdx.x, ty = threadIdx.y;
    int tid = ty*16 + tx;

    {
        unsigned sds = (unsigned)__cvta_generic_to_shared(ds);
        unsigned sws = (unsigned)__cvta_generic_to_shared(Ws);
        const float* dsrc = g_dx + (size_t)row0*256;
        #pragma unroll
        for (int r = 0; r < 8; r++) {
            int idx = r*256 + tid;
            cp16(sds + idx*16, dsrc + idx*4);
        }
        #pragma unroll
        for (int r = 0; r < 16; r++) {
            int idx = r*256 + tid;
            int wrow = idx >> 6, c4 = idx & 63;
            cp16(sws + (wrow*WDSTR + c4*4)*4, Wdec + wrow*256 + c4*4);
        }
        asm volatile("cp.async.commit_group;");
        asm volatile("cp.async.wait_group 0;");
    }
    __syncthreads();

    float acc[2][4] = {};
    int ty2 = ty*2;
    #pragma unroll 4
    for (int c = 0; c < 256; c += 4) {
        float4 dr[2];
        #pragma unroll
        for (int a = 0; a < 2; a++)
            dr[a] = *(const float4*)&ds[(ty2+a)*256 + c];
        #pragma unroll
        for (int b = 0; b < 4; b++) {
            const float* wp = &Ws[(b*16+tx)*WDSTR + c];
            float w0 = wp[0], w1 = wp[1], w2 = wp[2], w3 = wp[3];
            #pragma unroll
            for (int a = 0; a < 2; a++) {
                acc[a][b] = fmaf(dr[a].x, w0, acc[a][b]);
                acc[a][b] = fmaf(dr[a].y, w1, acc[a][b]);
                acc[a][b] = fmaf(dr[a].z, w2, acc[a][b]);
                acc[a][b] = fmaf(dr[a].w, w3, acc[a][b]);
            }
        }
    }
    #pragma unroll
    for (int b = 0; b < 4; b++) {
        float bb = bdec[b*16 + tx];
        #pragma unroll
        for (int a = 0; a < 2; a++)
            out[(size_t)(row0 + ty2 + a)*DD + b*16 + tx] = acc[a][b] + bb;
    }
}

// ---------------------------------------------------------------------------
extern "C" void kernel_launch(void* const* d_in, const int* in_sizes, int n_in,
                              void* d_out, int out_size)
{
    const float* x    = (const float*)d_in[0];
    // d_in[1] = edge (unused)
    const float* Wk   = (const float*)d_in[2];
    const float* bk   = (const float*)d_in[3];
    const float* Wq   = (const float*)d_in[4];
    const float* bq   = (const float*)d_in[5];
    const float* Wv   = (const float*)d_in[6];
    const float* bv   = (const float*)d_in[7];
    const float* Wdec = (const float*)d_in[8];
    const float* bdec = (const float*)d_in[9];
    float* out = (float*)d_out;

    cudaFuncSetAttribute(dec_kernel, cudaFuncAttributeMaxDynamicSharedMemorySize, DEC_SMEM);

    wprep<<<12, 256>>>(Wk, Wq, Wv);
    qkv_tc<<<dim3(MM/128, 3*HH, NB), 256>>>(x, bk, bq, bv);
    attn_tc<<<dim3(MM/128, HH, NB), 128>>>(x);
    dec_kernel<<<NB*MM/32, dim3(16,16), DEC_SMEM>>>(Wdec, bdec, out);
}

// round 16
// speedup vs baseline: 3.1422x; 1.0931x over previous
#include <cuda_runtime.h>
#include <cuda_bf16.h>
#include <cuda_fp16.h>

#define NB 16
#define MM 1024
#define DD 64
#define HH 4
#define NEG 0.2f

// ---------------- device scratch (allocation-free rule) ----------------
// dx as packed bf16 hi/lo planes: [n*M + m][128 words], word w = elems 2w,2w+1
__device__ unsigned g_dxh[NB*MM*128];
__device__ unsigned g_dxl[NB*MM*128];

// fp16 packed planes from qkv
__device__ unsigned g_Kp[NB*HH*MM*32];
__device__ unsigned g_Qp[NB*HH*MM*32];
__device__ unsigned g_Vp[NB*HH*DD*(MM/2)];

// Packed bf16-split projection weights (wprep), per (which*HH+h)
#define WSTR 40
#define WWORDS (64*WSTR)
__device__ unsigned g_Wbh[12*WWORDS];
__device__ unsigned g_Wbl[12*WWORDS];

// Packed bf16-split decoder weights: [64 e-rows][128 words] (k16 chunk packing)
__device__ unsigned g_Dbh[64*128];
__device__ unsigned g_Dbl[64*128];

// ---------------- helpers ----------------
__device__ __forceinline__ void mma_bf16(float* d,
                                         unsigned a0, unsigned a1, unsigned a2, unsigned a3,
                                         unsigned b0, unsigned b1) {
    asm volatile("mma.sync.aligned.m16n8k16.row.col.f32.bf16.bf16.f32 "
                 "{%0,%1,%2,%3}, {%4,%5,%6,%7}, {%8,%9}, {%0,%1,%2,%3};"
                 : "+f"(d[0]), "+f"(d[1]), "+f"(d[2]), "+f"(d[3])
                 : "r"(a0), "r"(a1), "r"(a2), "r"(a3), "r"(b0), "r"(b1));
}

__device__ __forceinline__ void mma_fp16(float* d,
                                         unsigned a0, unsigned a1, unsigned a2, unsigned a3,
                                         unsigned b0, unsigned b1) {
    asm volatile("mma.sync.aligned.m16n8k16.row.col.f32.f16.f16.f32 "
                 "{%0,%1,%2,%3}, {%4,%5,%6,%7}, {%8,%9}, {%0,%1,%2,%3};"
                 : "+f"(d[0]), "+f"(d[1]), "+f"(d[2]), "+f"(d[3])
                 : "r"(a0), "r"(a1), "r"(a2), "r"(a3), "r"(b0), "r"(b1));
}

__device__ __forceinline__ void cp16(unsigned dst_smem, const void* src) {
    asm volatile("cp.async.cg.shared.global [%0], [%1], 16;" :: "r"(dst_smem), "l"(src));
}

__device__ __forceinline__ void bsplit(float2 f, unsigned& hi, unsigned& lo) {
    __nv_bfloat162 h = __float22bfloat162_rn(f);
    float2 hf = __bfloat1622float2(h);
    __nv_bfloat162 l = __float22bfloat162_rn(make_float2(f.x - hf.x, f.y - hf.y));
    hi = *(unsigned*)&h;
    lo = *(unsigned*)&l;
}

__device__ __forceinline__ unsigned pack_h2(float a, float b) {
    __half2 h = __float22half2_rn(make_float2(a, b));   // a in low half
    return *(unsigned*)&h;
}

// ---------------------------------------------------------------------------
// Kernel 0: weight prep. blocks 0-11: K/Q/V heads; block 12: Wdec split.
// ---------------------------------------------------------------------------
__global__ __launch_bounds__(256) void wprep(
    const float* __restrict__ Wk,
    const float* __restrict__ Wq,
    const float* __restrict__ Wv,
    const float* __restrict__ Wdec)
{
    int bid = blockIdx.x;
    if (bid < 12) {
        int which = bid / HH, h = bid % HH;
        const float* W = ((which == 0) ? Wk : (which == 1) ? Wq : Wv) + h*DD*DD;
        unsigned* oh = g_Wbh + (size_t)bid*WWORDS;
        unsigned* ol = g_Wbl + (size_t)bid*WWORDS;
        for (int l = threadIdx.x; l < 64*32; l += 256) {
            int e = l >> 5, j = l & 31;
            float2 w = make_float2(W[e*64 + 2*j], W[e*64 + 2*j + 1]);
            unsigned hi, lo;
            bsplit(w, hi, lo);
            int c = j >> 3, jj = j & 7;
            int p = c*8 + 2*(jj & 3) + (jj >> 2);
            oh[e*WSTR + p] = hi;
            ol[e*WSTR + p] = lo;
        }
    } else {
        // Wdec: [64][256] -> per e-row 16 k-chunks x 8 packed words
        for (int l = threadIdx.x; l < 64*128; l += 256) {
            int e = l >> 7, j = l & 127;     // j = k/2
            float2 w = make_float2(Wdec[e*256 + 2*j], Wdec[e*256 + 2*j + 1]);
            unsigned hi, lo;
            bsplit(w, hi, lo);
            int c = j >> 3, jj = j & 7;
            int p = c*8 + 2*(jj & 3) + (jj >> 2);
            g_Dbh[e*128 + p] = hi;
            g_Dbl[e*128 + p] = lo;
        }
    }
}

// ---------------------------------------------------------------------------
// Kernel 1: bf16-split projections (unchanged from R15)
// ---------------------------------------------------------------------------
__global__ __launch_bounds__(256, 2) void qkv_tc(
    const float* __restrict__ x,
    const float* __restrict__ bk,
    const float* __restrict__ bq,
    const float* __restrict__ bv)
{
    __shared__ unsigned Wh[WWORDS];
    __shared__ unsigned Wl[WWORDS];
    int n = blockIdx.z;
    int which = blockIdx.y / HH;
    int h = blockIdx.y % HH;
    int mtile = blockIdx.x * 128;
    const float* bias = (which == 0) ? bk : (which == 1) ? bq : bv;
    int tid = threadIdx.x;
    int warp = tid >> 5, lane = tid & 31;
    int qr = lane >> 2, qc = lane & 3;

    {
        unsigned swh = (unsigned)__cvta_generic_to_shared(Wh);
        unsigned swl = (unsigned)__cvta_generic_to_shared(Wl);
        const unsigned* srcH = g_Wbh + (size_t)blockIdx.y*WWORDS;
        const unsigned* srcL = g_Wbl + (size_t)blockIdx.y*WWORDS;
        #pragma unroll
        for (int r = 0; r < 5; r++) {
            int idx = r*256 + tid;
            if (idx < 640) cp16(swh + idx*16, srcH + idx*4);
            else           cp16(swl + (idx-640)*16, srcL + (idx-640)*4);
        }
        asm volatile("cp.async.commit_group;");
    }

    int r0 = mtile + warp*16 + qr;
    const float* xg0 = x + (size_t)(n*MM + r0)*DD;
    const float* xg1 = xg0 + 8*DD;

    unsigned ah[4][4], al[4][4];
    #pragma unroll
    for (int c = 0; c < 4; c++) {
        float2 f00 = *(const float2*)&xg0[16*c + 2*qc];
        float2 f10 = *(const float2*)&xg1[16*c + 2*qc];
        float2 f01 = *(const float2*)&xg0[16*c + 2*qc + 8];
        float2 f11 = *(const float2*)&xg1[16*c + 2*qc + 8];
        bsplit(f00, ah[c][0], al[c][0]);
        bsplit(f10, ah[c][1], al[c][1]);
        bsplit(f01, ah[c][2], al[c][2]);
        bsplit(f11, ah[c][3], al[c][3]);
    }

    asm volatile("cp.async.wait_group 0;");
    __syncthreads();

    float o[8][4] = {};
    #pragma unroll
    for (int nt = 0; nt < 8; nt++) {
        int base = (nt*8 + qr)*WSTR + 2*qc;
        #pragma unroll
        for (int c = 0; c < 4; c++) {
            uint2 bh = *(const uint2*)&Wh[base + c*8];
            uint2 bl = *(const uint2*)&Wl[base + c*8];
            mma_bf16(o[nt], ah[c][0], ah[c][1], ah[c][2], ah[c][3], bh.x, bh.y);
            mma_bf16(o[nt], ah[c][0], ah[c][1], ah[c][2], ah[c][3], bl.x, bl.y);
            mma_bf16(o[nt], al[c][0], al[c][1], al[c][2], al[c][3], bh.x, bh.y);
        }
    }

    size_t hb = (size_t)(n*HH + h);
    if (which != 2) {
        unsigned* Pp = (which == 0 ? g_Kp : g_Qp) + hb*MM*32;
        #pragma unroll
        for (int nt = 0; nt < 8; nt++) {
            int c0 = nt*8 + 2*qc;
            float b0 = bias[h*DD + c0], b1 = bias[h*DD + c0 + 1];
            int w = 4*nt + qc;
            Pp[(size_t)r0*32 + w]     = pack_h2(o[nt][0]+b0, o[nt][1]+b1);
            Pp[(size_t)(r0+8)*32 + w] = pack_h2(o[nt][2]+b0, o[nt][3]+b1);
        }
    } else {
        unsigned* Vp = g_Vp + hb*DD*(MM/2);
        #pragma unroll
        for (int nt = 0; nt < 8; nt++) {
            int c0 = nt*8 + 2*qc;
            float b0 = bias[h*DD + c0], b1 = bias[h*DD + c0 + 1];
            float v0 = o[nt][0]+b0, v1 = o[nt][1]+b1;
            float v2 = o[nt][2]+b0, v3 = o[nt][3]+b1;
            float p0 = __shfl_down_sync(0xffffffffu, v0, 4);
            float p1 = __shfl_down_sync(0xffffffffu, v1, 4);
            float p2 = __shfl_down_sync(0xffffffffu, v2, 4);
            float p3 = __shfl_down_sync(0xffffffffu, v3, 4);
            if (!(qr & 1)) {
                int w0 = r0 >> 1, w1 = (r0 + 8) >> 1;
                Vp[(size_t)c0*(MM/2)     + w0] = pack_h2(v0, p0);
                Vp[(size_t)(c0+1)*(MM/2) + w0] = pack_h2(v1, p1);
                Vp[(size_t)c0*(MM/2)     + w1] = pack_h2(v2, p2);
                Vp[(size_t)(c0+1)*(MM/2) + w1] = pack_h2(v3, p3);
            }
        }
    }
}

// ---------------------------------------------------------------------------
// Kernel 2: fp16 flash attention (mainloop unchanged from R15); epilogue now
// writes dx as packed bf16 hi/lo planes for the tensor-core decoder.
// ---------------------------------------------------------------------------
#define TSW 36

__global__ __launch_bounds__(128, 2) void attn_tc(const float* __restrict__ x)
{
    __shared__ unsigned QS[2][64*TSW];
    __shared__ unsigned VS[2][64*TSW];

    int n = blockIdx.z, h = blockIdx.y;
    int itile = blockIdx.x * 128;
    int tid = threadIdx.x;
    int warp = tid >> 5, lane = tid & 31;
    int qr = lane >> 2, qc = lane & 3;
    size_t hb = (size_t)(n*HH + h);

    const unsigned* Kp = g_Kp + hb*MM*32;
    const unsigned* Qp = g_Qp + hb*MM*32;
    const unsigned* Vp = g_Vp + hb*DD*(MM/2);

    int rbase = itile + warp*32 + qr;

    unsigned ka[2][4][4];
    #pragma unroll
    for (int f = 0; f < 2; f++) {
        int r0 = rbase + f*16;
        #pragma unroll
        for (int c = 0; c < 4; c++) {
            ka[f][c][0] = Kp[(size_t)r0*32     + 8*c + qc];
            ka[f][c][1] = Kp[(size_t)(r0+8)*32 + 8*c + qc];
            ka[f][c][2] = Kp[(size_t)r0*32     + 8*c + 4 + qc];
            ka[f][c][3] = Kp[(size_t)(r0+8)*32 + 8*c + 4 + qc];
        }
    }

    float o[2][8][4] = {};
    float mr[2][2], lr[2][2];
    #pragma unroll
    for (int f = 0; f < 2; f++) { mr[f][0] = mr[f][1] = -1e30f; lr[f][0] = lr[f][1] = 0.f; }

    unsigned qb[2], vb[2];
    qb[0] = (unsigned)__cvta_generic_to_shared(QS[0]);
    qb[1] = (unsigned)__cvta_generic_to_shared(QS[1]);
    vb[0] = (unsigned)__cvta_generic_to_shared(VS[0]);
    vb[1] = (unsigned)__cvta_generic_to_shared(VS[1]);

    #pragma unroll
    for (int i = 0; i < 4; i++) {
        int idx = i*128 + tid;
        int row = idx >> 3, c4 = idx & 7;
        unsigned dofs = (row*TSW + c4*4)*4;
        cp16(qb[0] + dofs, Qp + (size_t)row*32 + c4*4);
        cp16(vb[0] + dofs, Vp + (size_t)row*(MM/2) + c4*4);
    }
    asm volatile("cp.async.commit_group;");

    for (int jt = 0; jt < 16; jt++) {
        int buf = jt & 1;
        if (jt < 15) {
            int nb = buf ^ 1;
            const unsigned* qg = Qp + (size_t)(jt+1)*64*32;
            const unsigned* vg = Vp + (jt+1)*32;
            #pragma unroll
            for (int i = 0; i < 4; i++) {
                int idx = i*128 + tid;
                int row = idx >> 3, c4 = idx & 7;
                unsigned dofs = (row*TSW + c4*4)*4;
                cp16(qb[nb] + dofs, qg + (size_t)row*32 + c4*4);
                cp16(vb[nb] + dofs, vg + (size_t)row*(MM/2) + c4*4);
            }
            asm volatile("cp.async.commit_group;");
            asm volatile("cp.async.wait_group 1;");
        } else {
            asm volatile("cp.async.wait_group 0;");
        }
        __syncthreads();

        const unsigned* Qc = QS[buf];
        const unsigned* Vc = VS[buf];

        float s[2][8][4];
        #pragma unroll
        for (int nt = 0; nt < 8; nt++) {
            s[0][nt][0] = s[0][nt][1] = s[0][nt][2] = s[0][nt][3] = 0.f;
            s[1][nt][0] = s[1][nt][1] = s[1][nt][2] = s[1][nt][3] = 0.f;
            const unsigned* qrow = &Qc[(nt*8 + qr)*TSW];
            #pragma unroll
            for (int c = 0; c < 4; c++) {
                unsigned b0 = qrow[8*c + qc];
                unsigned b1 = qrow[8*c + 4 + qc];
                #pragma unroll
                for (int f = 0; f < 2; f++)
                    mma_fp16(s[f][nt], ka[f][c][0], ka[f][c][1], ka[f][c][2], ka[f][c][3], b0, b1);
            }
        }

        #pragma unroll
        for (int f = 0; f < 2; f++) {
            float m0 = -1e30f, m1 = -1e30f;
            #pragma unroll
            for (int nt = 0; nt < 8; nt++) {
                #pragma unroll
                for (int c = 0; c < 4; c++)
                    s[f][nt][c] = s[f][nt][c] > 0.f ? s[f][nt][c] : NEG*s[f][nt][c];
                m0 = fmaxf(m0, fmaxf(s[f][nt][0], s[f][nt][1]));
                m1 = fmaxf(m1, fmaxf(s[f][nt][2], s[f][nt][3]));
            }
            m0 = fmaxf(m0, __shfl_xor_sync(0xffffffffu, m0, 1));
            m0 = fmaxf(m0, __shfl_xor_sync(0xffffffffu, m0, 2));
            m1 = fmaxf(m1, __shfl_xor_sync(0xffffffffu, m1, 1));
            m1 = fmaxf(m1, __shfl_xor_sync(0xffffffffu, m1, 2));
            float nm0 = fmaxf(mr[f][0], m0), nm1 = fmaxf(mr[f][1], m1);
            float c0 = __expf(mr[f][0] - nm0), c1 = __expf(mr[f][1] - nm1);
            mr[f][0] = nm0; mr[f][1] = nm1;
            float a0 = 0.f, a1 = 0.f;
            #pragma unroll
            for (int nt = 0; nt < 8; nt++) {
                s[f][nt][0] = __expf(s[f][nt][0] - nm0);
                s[f][nt][1] = __expf(s[f][nt][1] - nm0);
                s[f][nt][2] = __expf(s[f][nt][2] - nm1);
                s[f][nt][3] = __expf(s[f][nt][3] - nm1);
                a0 += s[f][nt][0] + s[f][nt][1];
                a1 += s[f][nt][2] + s[f][nt][3];
                o[f][nt][0] *= c0; o[f][nt][1] *= c0; o[f][nt][2] *= c1; o[f][nt][3] *= c1;
            }
            a0 += __shfl_xor_sync(0xffffffffu, a0, 1);
            a0 += __shfl_xor_sync(0xffffffffu, a0, 2);
            a1 += __shfl_xor_sync(0xffffffffu, a1, 1);
            a1 += __shfl_xor_sync(0xffffffffu, a1, 2);
            lr[f][0] = lr[f][0]*c0 + a0;
            lr[f][1] = lr[f][1]*c1 + a1;
        }

        #pragma unroll
        for (int c = 0; c < 4; c++) {
            unsigned pa[2][4];
            #pragma unroll
            for (int f = 0; f < 2; f++) {
                pa[f][0] = pack_h2(s[f][2*c][0],   s[f][2*c][1]);
                pa[f][1] = pack_h2(s[f][2*c][2],   s[f][2*c][3]);
                pa[f][2] = pack_h2(s[f][2*c+1][0], s[f][2*c+1][1]);
                pa[f][3] = pack_h2(s[f][2*c+1][2], s[f][2*c+1][3]);
            }
            #pragma unroll
            for (int nt = 0; nt < 8; nt++) {
                const unsigned* vrow = &Vc[(nt*8 + qr)*TSW];
                unsigned b0 = vrow[8*c + qc];
                unsigned b1 = vrow[8*c + 4 + qc];
                #pragma unroll
                for (int f = 0; f < 2; f++)
                    mma_fp16(o[f][nt], pa[f][0], pa[f][1], pa[f][2], pa[f][3], b0, b1);
            }
        }
        __syncthreads();
    }

    // ---- epilogue: leaky(o/l) - x -> packed bf16 hi/lo dx planes ----
    #pragma unroll
    for (int f = 0; f < 2; f++) {
        float inv0 = 1.f / lr[f][0], inv1 = 1.f / lr[f][1];
        size_t gm0 = (size_t)(n*MM + rbase + f*16);
        size_t gm1 = gm0 + 8;
        const float* x0 = x + gm0*DD;
        const float* x1 = x + gm1*DD;
        unsigned* dh0 = g_dxh + gm0*128 + h*32;
        unsigned* dl0 = g_dxl + gm0*128 + h*32;
        unsigned* dh1 = g_dxh + gm1*128 + h*32;
        unsigned* dl1 = g_dxl + gm1*128 + h*32;
        #pragma unroll
        for (int nt = 0; nt < 8; nt++) {
            int cb = nt*8 + 2*qc;
            float2 xv0 = *(const float2*)&x0[cb];
            float2 xv1 = *(const float2*)&x1[cb];
            float v00 = o[f][nt][0]*inv0; v00 = (v00 > 0.f ? v00 : NEG*v00) - xv0.x;
            float v01 = o[f][nt][1]*inv0; v01 = (v01 > 0.f ? v01 : NEG*v01) - xv0.y;
            float v10 = o[f][nt][2]*inv1; v10 = (v10 > 0.f ? v10 : NEG*v10) - xv1.x;
            float v11 = o[f][nt][3]*inv1; v11 = (v11 > 0.f ? v11 : NEG*v11) - xv1.y;
            unsigned uh, ul;
            int w = nt*4 + qc;
            bsplit(make_float2(v00, v01), uh, ul);
            dh0[w] = uh; dl0[w] = ul;
            bsplit(make_float2(v10, v11), uh, ul);
            dh1[w] = uh; dl1[w] = ul;
        }
    }
}

// ---------------------------------------------------------------------------
// Kernel 3: tensor-core decoder (bf16 3-product split, m16n8k16).
// grid NB*MM/64 = 256 CTAs, block 128 (4 warps x 16 rows). Wdec hi/lo in smem
// (stride 136 words, conflict-free LDS.64); A-frags streamed from dx planes.
// ---------------------------------------------------------------------------
#define DWSTR 136
#define DEC_SMEM (2*64*DWSTR*4)   // 69632 B

__global__ __launch_bounds__(128, 2) void dec_tc(
    const float* __restrict__ bdec, float* __restrict__ out)
{
    extern __shared__ unsigned dsm[];
    unsigned* Dh = dsm;
    unsigned* Dl = dsm + 64*DWSTR;
    int row0 = blockIdx.x * 64;
    int tid = threadIdx.x;
    int warp = tid >> 5, lane = tid & 31;
    int qr = lane >> 2, qc = lane & 3;

    {
        unsigned sh = (unsigned)__cvta_generic_to_shared(Dh);
        unsigned sl = (unsigned)__cvta_generic_to_shared(Dl);
        #pragma unroll
        for (int i = 0; i < 16; i++) {
            int idx = i*128 + tid;          // 2048 chunks per plane
            int r = idx >> 5, c4 = idx & 31;
            unsigned dofs = (r*DWSTR + c4*4)*4;
            cp16(sh + dofs, g_Dbh + r*128 + c4*4);
            cp16(sl + dofs, g_Dbl + r*128 + c4*4);
        }
        asm volatile("cp.async.commit_group;");
    }

    int r0 = row0 + warp*16 + qr;
    const unsigned* axh0 = g_dxh + (size_t)r0*128;
    const unsigned* axl0 = g_dxl + (size_t)r0*128;
    const unsigned* axh1 = axh0 + 8*128;
    const unsigned* axl1 = axl0 + 8*128;

    asm volatile("cp.async.wait_group 0;");
    __syncthreads();

    float o[8][4] = {};
    #pragma unroll
    for (int c = 0; c < 16; c++) {
        unsigned a0h = axh0[8*c + qc],     a1h = axh1[8*c + qc];
        unsigned a2h = axh0[8*c + 4 + qc], a3h = axh1[8*c + 4 + qc];
        unsigned a0l = axl0[8*c + qc],     a1l = axl1[8*c + qc];
        unsigned a2l = axl0[8*c + 4 + qc], a3l = axl1[8*c + 4 + qc];
        #pragma unroll
        for (int nt = 0; nt < 8; nt++) {
            int base = (nt*8 + qr)*DWSTR + c*8 + 2*qc;
            uint2 bh = *(const uint2*)&Dh[base];
            uint2 bl = *(const uint2*)&Dl[base];
            mma_bf16(o[nt], a0h, a1h, a2h, a3h, bh.x, bh.y);
            mma_bf16(o[nt], a0h, a1h, a2h, a3h, bl.x, bl.y);
            mma_bf16(o[nt], a0l, a1l, a2l, a3l, bh.x, bh.y);
        }
    }

    #pragma unroll
    for (int nt = 0; nt < 8; nt++) {
        int e0 = nt*8 + 2*qc;
        float b0 = bdec[e0], b1 = bdec[e0 + 1];
        *(float2*)&out[(size_t)r0*DD + e0]     = make_float2(o[nt][0]+b0, o[nt][1]+b1);
        *(float2*)&out[(size_t)(r0+8)*DD + e0] = make_float2(o[nt][2]+b0, o[nt][3]+b1);
    }
}

// ---------------------------------------------------------------------------
extern "C" void kernel_launch(void* const* d_in, const int* in_sizes, int n_in,
                              void* d_out, int out_size)
{
    const float* x    = (const float*)d_in[0];
    // d_in[1] = edge (unused)
    const float* Wk   = (const float*)d_in[2];
    const float* bk   = (const float*)d_in[3];
    const float* Wq   = (const float*)d_in[4];
    const float* bq   = (const float*)d_in[5];
    const float* Wv   = (const float*)d_in[6];
    const float* bv   = (const float*)d_in[7];
    const float* Wdec = (const float*)d_in[8];
    const float* bdec = (const float*)d_in[9];
    float* out = (float*)d_out;

    cudaFuncSetAttribute(dec_tc, cudaFuncAttributeMaxDynamicSharedMemorySize, DEC_SMEM);

    wprep<<<13, 256>>>(Wk, Wq, Wv, Wdec);
    qkv_tc<<<dim3(MM/128, 3*HH, NB), 256>>>(x, bk, bq, bv);
    attn_tc<<<dim3(MM/128, HH, NB), 128>>>(x);
    dec_tc<<<NB*MM/64, 128, DEC_SMEM>>>(bdec, out);
}

// round 17
// speedup vs baseline: 3.2063x; 1.0204x over previous
#include <cuda_runtime.h>
#include <cuda_bf16.h>
#include <cuda_fp16.h>

#define NB 16
#define MM 1024
#define DD 64
#define HH 4
#define NEG 0.2f

// ---------------- device scratch (allocation-free rule) ----------------
// dx as packed bf16 hi/lo planes: [n*M + m][128 words]
__device__ unsigned g_dxh[NB*MM*128];
__device__ unsigned g_dxl[NB*MM*128];

// fp16 packed planes from qkv
__device__ unsigned g_Kp[NB*HH*MM*32];
__device__ unsigned g_Qp[NB*HH*MM*32];
__device__ unsigned g_Vp[NB*HH*DD*(MM/2)];

// Packed bf16-split projection weights (wprep), per (which*HH+h)
#define WSTR 40
#define WWORDS (64*WSTR)
__device__ unsigned g_Wbh[12*WWORDS];
__device__ unsigned g_Wbl[12*WWORDS];

// Packed bf16-split decoder weights: [64 e-rows][128 words]
__device__ unsigned g_Dbh[64*128];
__device__ unsigned g_Dbl[64*128];

// ---------------- helpers ----------------
__device__ __forceinline__ void mma_bf16(float* d,
                                         unsigned a0, unsigned a1, unsigned a2, unsigned a3,
                                         unsigned b0, unsigned b1) {
    asm volatile("mma.sync.aligned.m16n8k16.row.col.f32.bf16.bf16.f32 "
                 "{%0,%1,%2,%3}, {%4,%5,%6,%7}, {%8,%9}, {%0,%1,%2,%3};"
                 : "+f"(d[0]), "+f"(d[1]), "+f"(d[2]), "+f"(d[3])
                 : "r"(a0), "r"(a1), "r"(a2), "r"(a3), "r"(b0), "r"(b1));
}

__device__ __forceinline__ void mma_fp16(float* d,
                                         unsigned a0, unsigned a1, unsigned a2, unsigned a3,
                                         unsigned b0, unsigned b1) {
    asm volatile("mma.sync.aligned.m16n8k16.row.col.f32.f16.f16.f32 "
                 "{%0,%1,%2,%3}, {%4,%5,%6,%7}, {%8,%9}, {%0,%1,%2,%3};"
                 : "+f"(d[0]), "+f"(d[1]), "+f"(d[2]), "+f"(d[3])
                 : "r"(a0), "r"(a1), "r"(a2), "r"(a3), "r"(b0), "r"(b1));
}

__device__ __forceinline__ void cp16(unsigned dst_smem, const void* src) {
    asm volatile("cp.async.cg.shared.global [%0], [%1], 16;" :: "r"(dst_smem), "l"(src));
}

__device__ __forceinline__ void bsplit(float2 f, unsigned& hi, unsigned& lo) {
    __nv_bfloat162 h = __float22bfloat162_rn(f);
    float2 hf = __bfloat1622float2(h);
    __nv_bfloat162 l = __float22bfloat162_rn(make_float2(f.x - hf.x, f.y - hf.y));
    hi = *(unsigned*)&h;
    lo = *(unsigned*)&l;
}

__device__ __forceinline__ unsigned pack_h2(float a, float b) {
    __half2 h = __float22half2_rn(make_float2(a, b));
    return *(unsigned*)&h;
}

// ---------------------------------------------------------------------------
// Kernel 0: weight prep (unchanged from R16)
// ---------------------------------------------------------------------------
__global__ __launch_bounds__(256) void wprep(
    const float* __restrict__ Wk,
    const float* __restrict__ Wq,
    const float* __restrict__ Wv,
    const float* __restrict__ Wdec)
{
    int bid = blockIdx.x;
    if (bid < 12) {
        int which = bid / HH, h = bid % HH;
        const float* W = ((which == 0) ? Wk : (which == 1) ? Wq : Wv) + h*DD*DD;
        unsigned* oh = g_Wbh + (size_t)bid*WWORDS;
        unsigned* ol = g_Wbl + (size_t)bid*WWORDS;
        for (int l = threadIdx.x; l < 64*32; l += 256) {
            int e = l >> 5, j = l & 31;
            float2 w = make_float2(W[e*64 + 2*j], W[e*64 + 2*j + 1]);
            unsigned hi, lo;
            bsplit(w, hi, lo);
            int c = j >> 3, jj = j & 7;
            int p = c*8 + 2*(jj & 3) + (jj >> 2);
            oh[e*WSTR + p] = hi;
            ol[e*WSTR + p] = lo;
        }
    } else {
        for (int l = threadIdx.x; l < 64*128; l += 256) {
            int e = l >> 7, j = l & 127;
            float2 w = make_float2(Wdec[e*256 + 2*j], Wdec[e*256 + 2*j + 1]);
            unsigned hi, lo;
            bsplit(w, hi, lo);
            int c = j >> 3, jj = j & 7;
            int p = c*8 + 2*(jj & 3) + (jj >> 2);
            g_Dbh[e*128 + p] = hi;
            g_Dbl[e*128 + p] = lo;
        }
    }
}

// ---------------------------------------------------------------------------
// Kernel 1: fused K/Q/V projections. grid (M/128, H, N) = 512 CTAs, block 256.
// x loaded + split once; all six W planes staged in one prologue; the three
// projections computed sequentially reusing the A-frags.
// ---------------------------------------------------------------------------
#define QKV_SMEM (6*WWORDS*4)   // 61440 B

__global__ __launch_bounds__(256, 2) void qkv_tc(
    const float* __restrict__ x,
    const float* __restrict__ bk,
    const float* __restrict__ bq,
    const float* __restrict__ bv)
{
    extern __shared__ unsigned wsm[];   // [6][WWORDS]: Wh K,Q,V then Wl K,Q,V
    int n = blockIdx.z;
    int h = blockIdx.y;
    int mtile = blockIdx.x * 128;
    int tid = threadIdx.x;
    int warp = tid >> 5, lane = tid & 31;
    int qr = lane >> 2, qc = lane & 3;

    {
        unsigned sb = (unsigned)__cvta_generic_to_shared(wsm);
        #pragma unroll
        for (int r = 0; r < 15; r++) {
            int idx = r*256 + tid;            // 3840 16B-chunks
            int plane = idx / 640, c = idx - plane*640;
            const unsigned* src = (plane < 3)
                ? g_Wbh + (size_t)(plane*HH + h)*WWORDS + c*4
                : g_Wbl + (size_t)((plane-3)*HH + h)*WWORDS + c*4;
            cp16(sb + (plane*WWORDS + c*4)*4, src);
        }
        asm volatile("cp.async.commit_group;");
    }

    int r0 = mtile + warp*16 + qr;
    const float* xg0 = x + (size_t)(n*MM + r0)*DD;
    const float* xg1 = xg0 + 8*DD;

    unsigned ah[4][4], al[4][4];
    #pragma unroll
    for (int c = 0; c < 4; c++) {
        float2 f00 = *(const float2*)&xg0[16*c + 2*qc];
        float2 f10 = *(const float2*)&xg1[16*c + 2*qc];
        float2 f01 = *(const float2*)&xg0[16*c + 2*qc + 8];
        float2 f11 = *(const float2*)&xg1[16*c + 2*qc + 8];
        bsplit(f00, ah[c][0], al[c][0]);
        bsplit(f10, ah[c][1], al[c][1]);
        bsplit(f01, ah[c][2], al[c][2]);
        bsplit(f11, ah[c][3], al[c][3]);
    }

    asm volatile("cp.async.wait_group 0;");
    __syncthreads();

    size_t hb = (size_t)(n*HH + h);

    #pragma unroll
    for (int which = 0; which < 3; which++) {
        const unsigned* Wh = wsm + which*WWORDS;
        const unsigned* Wl = wsm + (3+which)*WWORDS;
        const float* bias = (which == 0) ? bk : (which == 1) ? bq : bv;

        float o[8][4] = {};
        #pragma unroll
        for (int nt = 0; nt < 8; nt++) {
            int base = (nt*8 + qr)*WSTR + 2*qc;
            #pragma unroll
            for (int c = 0; c < 4; c++) {
                uint2 bh = *(const uint2*)&Wh[base + c*8];
                uint2 bl = *(const uint2*)&Wl[base + c*8];
                mma_bf16(o[nt], ah[c][0], ah[c][1], ah[c][2], ah[c][3], bh.x, bh.y);
                mma_bf16(o[nt], ah[c][0], ah[c][1], ah[c][2], ah[c][3], bl.x, bl.y);
                mma_bf16(o[nt], al[c][0], al[c][1], al[c][2], al[c][3], bh.x, bh.y);
            }
        }

        if (which != 2) {
            unsigned* Pp = (which == 0 ? g_Kp : g_Qp) + hb*MM*32;
            #pragma unroll
            for (int nt = 0; nt < 8; nt++) {
                int c0 = nt*8 + 2*qc;
                float b0 = bias[h*DD + c0], b1 = bias[h*DD + c0 + 1];
                int w = 4*nt + qc;
                Pp[(size_t)r0*32 + w]     = pack_h2(o[nt][0]+b0, o[nt][1]+b1);
                Pp[(size_t)(r0+8)*32 + w] = pack_h2(o[nt][2]+b0, o[nt][3]+b1);
            }
        } else {
            unsigned* Vp = g_Vp + hb*DD*(MM/2);
            #pragma unroll
            for (int nt = 0; nt < 8; nt++) {
                int c0 = nt*8 + 2*qc;
                float b0 = bias[h*DD + c0], b1 = bias[h*DD + c0 + 1];
                float v0 = o[nt][0]+b0, v1 = o[nt][1]+b1;
                float v2 = o[nt][2]+b0, v3 = o[nt][3]+b1;
                float p0 = __shfl_down_sync(0xffffffffu, v0, 4);
                float p1 = __shfl_down_sync(0xffffffffu, v1, 4);
                float p2 = __shfl_down_sync(0xffffffffu, v2, 4);
                float p3 = __shfl_down_sync(0xffffffffu, v3, 4);
                if (!(qr & 1)) {
                    int w0 = r0 >> 1, w1 = (r0 + 8) >> 1;
                    Vp[(size_t)c0*(MM/2)     + w0] = pack_h2(v0, p0);
                    Vp[(size_t)(c0+1)*(MM/2) + w0] = pack_h2(v1, p1);
                    Vp[(size_t)c0*(MM/2)     + w1] = pack_h2(v2, p2);
                    Vp[(size_t)(c0+1)*(MM/2) + w1] = pack_h2(v3, p3);
                }
            }
        }
    }
}

// ---------------------------------------------------------------------------
// Kernel 2: fp16 flash attention (unchanged from R16)
// ---------------------------------------------------------------------------
#define TSW 36

__global__ __launch_bounds__(128, 2) void attn_tc(const float* __restrict__ x)
{
    __shared__ unsigned QS[2][64*TSW];
    __shared__ unsigned VS[2][64*TSW];

    int n = blockIdx.z, h = blockIdx.y;
    int itile = blockIdx.x * 128;
    int tid = threadIdx.x;
    int warp = tid >> 5, lane = tid & 31;
    int qr = lane >> 2, qc = lane & 3;
    size_t hb = (size_t)(n*HH + h);

    const unsigned* Kp = g_Kp + hb*MM*32;
    const unsigned* Qp = g_Qp + hb*MM*32;
    const unsigned* Vp = g_Vp + hb*DD*(MM/2);

    int rbase = itile + warp*32 + qr;

    unsigned ka[2][4][4];
    #pragma unroll
    for (int f = 0; f < 2; f++) {
        int r0 = rbase + f*16;
        #pragma unroll
        for (int c = 0; c < 4; c++) {
            ka[f][c][0] = Kp[(size_t)r0*32     + 8*c + qc];
            ka[f][c][1] = Kp[(size_t)(r0+8)*32 + 8*c + qc];
            ka[f][c][2] = Kp[(size_t)r0*32     + 8*c + 4 + qc];
            ka[f][c][3] = Kp[(size_t)(r0+8)*32 + 8*c + 4 + qc];
        }
    }

    float o[2][8][4] = {};
    float mr[2][2], lr[2][2];
    #pragma unroll
    for (int f = 0; f < 2; f++) { mr[f][0] = mr[f][1] = -1e30f; lr[f][0] = lr[f][1] = 0.f; }

    unsigned qb[2], vb[2];
    qb[0] = (unsigned)__cvta_generic_to_shared(QS[0]);
    qb[1] = (unsigned)__cvta_generic_to_shared(QS[1]);
    vb[0] = (unsigned)__cvta_generic_to_shared(VS[0]);
    vb[1] = (unsigned)__cvta_generic_to_shared(VS[1]);

    #pragma unroll
    for (int i = 0; i < 4; i++) {
        int idx = i*128 + tid;
        int row = idx >> 3, c4 = idx & 7;
        unsigned dofs = (row*TSW + c4*4)*4;
        cp16(qb[0] + dofs, Qp + (size_t)row*32 + c4*4);
        cp16(vb[0] + dofs, Vp + (size_t)row*(MM/2) + c4*4);
    }
    asm volatile("cp.async.commit_group;");

    for (int jt = 0; jt < 16; jt++) {
        int buf = jt & 1;
        if (jt < 15) {
            int nb = buf ^ 1;
            const unsigned* qg = Qp + (size_t)(jt+1)*64*32;
            const unsigned* vg = Vp + (jt+1)*32;
            #pragma unroll
            for (int i = 0; i < 4; i++) {
                int idx = i*128 + tid;
                int row = idx >> 3, c4 = idx & 7;
                unsigned dofs = (row*TSW + c4*4)*4;
                cp16(qb[nb] + dofs, qg + (size_t)row*32 + c4*4);
                cp16(vb[nb] + dofs, vg + (size_t)row*(MM/2) + c4*4);
            }
            asm volatile("cp.async.commit_group;");
            asm volatile("cp.async.wait_group 1;");
        } else {
            asm volatile("cp.async.wait_group 0;");
        }
        __syncthreads();

        const unsigned* Qc = QS[buf];
        const unsigned* Vc = VS[buf];

        float s[2][8][4];
        #pragma unroll
        for (int nt = 0; nt < 8; nt++) {
            s[0][nt][0] = s[0][nt][1] = s[0][nt][2] = s[0][nt][3] = 0.f;
            s[1][nt][0] = s[1][nt][1] = s[1][nt][2] = s[1][nt][3] = 0.f;
            const unsigned* qrow = &Qc[(nt*8 + qr)*TSW];
            #pragma unroll
            for (int c = 0; c < 4; c++) {
                unsigned b0 = qrow[8*c + qc];
                unsigned b1 = qrow[8*c + 4 + qc];
                #pragma unroll
                for (int f = 0; f < 2; f++)
                    mma_fp16(s[f][nt], ka[f][c][0], ka[f][c][1], ka[f][c][2], ka[f][c][3], b0, b1);
            }
        }

        #pragma unroll
        for (int f = 0; f < 2; f++) {
            float m0 = -1e30f, m1 = -1e30f;
            #pragma unroll
            for (int nt = 0; nt < 8; nt++) {
                #pragma unroll
                for (int c = 0; c < 4; c++)
                    s[f][nt][c] = s[f][nt][c] > 0.f ? s[f][nt][c] : NEG*s[f][nt][c];
                m0 = fmaxf(m0, fmaxf(s[f][nt][0], s[f][nt][1]));
                m1 = fmaxf(m1, fmaxf(s[f][nt][2], s[f][nt][3]));
            }
            m0 = fmaxf(m0, __shfl_xor_sync(0xffffffffu, m0, 1));
            m0 = fmaxf(m0, __shfl_xor_sync(0xffffffffu, m0, 2));
            m1 = fmaxf(m1, __shfl_xor_sync(0xffffffffu, m1, 1));
            m1 = fmaxf(m1, __shfl_xor_sync(0xffffffffu, m1, 2));
            float nm0 = fmaxf(mr[f][0], m0), nm1 = fmaxf(mr[f][1], m1);
            float c0 = __expf(mr[f][0] - nm0), c1 = __expf(mr[f][1] - nm1);
            mr[f][0] = nm0; mr[f][1] = nm1;
            float a0 = 0.f, a1 = 0.f;
            #pragma unroll
            for (int nt = 0; nt < 8; nt++) {
                s[f][nt][0] = __expf(s[f][nt][0] - nm0);
                s[f][nt][1] = __expf(s[f][nt][1] - nm0);
                s[f][nt][2] = __expf(s[f][nt][2] - nm1);
                s[f][nt][3] = __expf(s[f][nt][3] - nm1);
                a0 += s[f][nt][0] + s[f][nt][1];
                a1 += s[f][nt][2] + s[f][nt][3];
                o[f][nt][0] *= c0; o[f][nt][1] *= c0; o[f][nt][2] *= c1; o[f][nt][3] *= c1;
            }
            a0 += __shfl_xor_sync(0xffffffffu, a0, 1);
            a0 += __shfl_xor_sync(0xffffffffu, a0, 2);
            a1 += __shfl_xor_sync(0xffffffffu, a1, 1);
            a1 += __shfl_xor_sync(0xffffffffu, a1, 2);
            lr[f][0] = lr[f][0]*c0 + a0;
            lr[f][1] = lr[f][1]*c1 + a1;
        }

        #pragma unroll
        for (int c = 0; c < 4; c++) {
            unsigned pa[2][4];
            #pragma unroll
            for (int f = 0; f < 2; f++) {
                pa[f][0] = pack_h2(s[f][2*c][0],   s[f][2*c][1]);
                pa[f][1] = pack_h2(s[f][2*c][2],   s[f][2*c][3]);
                pa[f][2] = pack_h2(s[f][2*c+1][0], s[f][2*c+1][1]);
                pa[f][3] = pack_h2(s[f][2*c+1][2], s[f][2*c+1][3]);
            }
            #pragma unroll
            for (int nt = 0; nt < 8; nt++) {
                const unsigned* vrow = &Vc[(nt*8 + qr)*TSW];
                unsigned b0 = vrow[8*c + qc];
                unsigned b1 = vrow[8*c + 4 + qc];
                #pragma unroll
                for (int f = 0; f < 2; f++)
                    mma_fp16(o[f][nt], pa[f][0], pa[f][1], pa[f][2], pa[f][3], b0, b1);
            }
        }
        __syncthreads();
    }

    #pragma unroll
    for (int f = 0; f < 2; f++) {
        float inv0 = 1.f / lr[f][0], inv1 = 1.f / lr[f][1];
        size_t gm0 = (size_t)(n*MM + rbase + f*16);
        size_t gm1 = gm0 + 8;
        const float* x0 = x + gm0*DD;
        const float* x1 = x + gm1*DD;
        unsigned* dh0 = g_dxh + gm0*128 + h*32;
        unsigned* dl0 = g_dxl + gm0*128 + h*32;
        unsigned* dh1 = g_dxh + gm1*128 + h*32;
        unsigned* dl1 = g_dxl + gm1*128 + h*32;
        #pragma unroll
        for (int nt = 0; nt < 8; nt++) {
            int cb = nt*8 + 2*qc;
            float2 xv0 = *(const float2*)&x0[cb];
            float2 xv1 = *(const float2*)&x1[cb];
            float v00 = o[f][nt][0]*inv0; v00 = (v00 > 0.f ? v00 : NEG*v00) - xv0.x;
            float v01 = o[f][nt][1]*inv0; v01 = (v01 > 0.f ? v01 : NEG*v01) - xv0.y;
            float v10 = o[f][nt][2]*inv1; v10 = (v10 > 0.f ? v10 : NEG*v10) - xv1.x;
            float v11 = o[f][nt][3]*inv1; v11 = (v11 > 0.f ? v11 : NEG*v11) - xv1.y;
            unsigned uh, ul;
            int w = nt*4 + qc;
            bsplit(make_float2(v00, v01), uh, ul);
            dh0[w] = uh; dl0[w] = ul;
            bsplit(make_float2(v10, v11), uh, ul);
            dh1[w] = uh; dl1[w] = ul;
        }
    }
}

// ---------------------------------------------------------------------------
// Kernel 3: tensor-core decoder, 128 rows/CTA, 256 threads, grid 128
// (single wave; Wdec staged once per CTA).
// ---------------------------------------------------------------------------
#define DWSTR 136
#define DEC_SMEM (2*64*DWSTR*4)   // 69632 B

__global__ __launch_bounds__(256, 2) void dec_tc(
    const float* __restrict__ bdec, float* __restrict__ out)
{
    extern __shared__ unsigned dsm[];
    unsigned* Dh = dsm;
    unsigned* Dl = dsm + 64*DWSTR;
    int row0 = blockIdx.x * 128;
    int tid = threadIdx.x;
    int warp = tid >> 5, lane = tid & 31;
    int qr = lane >> 2, qc = lane & 3;

    {
        unsigned sh = (unsigned)__cvta_generic_to_shared(Dh);
        unsigned sl = (unsigned)__cvta_generic_to_shared(Dl);
        #pragma unroll
        for (int i = 0; i < 8; i++) {
            int idx = i*256 + tid;          // 2048 chunks per plane
            int r = idx >> 5, c4 = idx & 31;
            unsigned dofs = (r*DWSTR + c4*4)*4;
            cp16(sh + dofs, g_Dbh + r*128 + c4*4);
            cp16(sl + dofs, g_Dbl + r*128 + c4*4);
        }
        asm volatile("cp.async.commit_group;");
    }

    int r0 = row0 + warp*16 + qr;
    const unsigned* axh0 = g_dxh + (size_t)r0*128;
    const unsigned* axl0 = g_dxl + (size_t)r0*128;
    const unsigned* axh1 = axh0 + 8*128;
    const unsigned* axl1 = axl0 + 8*128;

    asm volatile("cp.async.wait_group 0;");
    __syncthreads();

    float o[8][4] = {};
    #pragma unroll
    for (int c = 0; c < 16; c++) {
        unsigned a0h = axh0[8*c + qc],     a1h = axh1[8*c + qc];
        unsigned a2h = axh0[8*c + 4 + qc], a3h = axh1[8*c + 4 + qc];
        unsigned a0l = axl0[8*c + qc],     a1l = axl1[8*c + qc];
        unsigned a2l = axl0[8*c + 4 + qc], a3l = axl1[8*c + 4 + qc];
        #pragma unroll
        for (int nt = 0; nt < 8; nt++) {
            int base = (nt*8 + qr)*DWSTR + c*8 + 2*qc;
            uint2 bh = *(const uint2*)&Dh[base];
            uint2 bl = *(const uint2*)&Dl[base];
            mma_bf16(o[nt], a0h, a1h, a2h, a3h, bh.x, bh.y);
            mma_bf16(o[nt], a0h, a1h, a2h, a3h, bl.x, bl.y);
            mma_bf16(o[nt], a0l, a1l, a2l, a3l, bh.x, bh.y);
        }
    }

    #pragma unroll
    for (int nt = 0; nt < 8; nt++) {
        int e0 = nt*8 + 2*qc;
        float b0 = bdec[e0], b1 = bdec[e0 + 1];
        *(float2*)&out[(size_t)r0*DD + e0]     = make_float2(o[nt][0]+b0, o[nt][1]+b1);
        *(float2*)&out[(size_t)(r0+8)*DD + e0] = make_float2(o[nt][2]+b0, o[nt][3]+b1);
    }
}

// ---------------------------------------------------------------------------
extern "C" void kernel_launch(void* const* d_in, const int* in_sizes, int n_in,
                              void* d_out, int out_size)
{
    const float* x    = (const float*)d_in[0];
    // d_in[1] = edge (unused)
    const float* Wk   = (const float*)d_in[2];
    const float* bk   = (const float*)d_in[3];
    const float* Wq   = (const float*)d_in[4];
    const float* bq   = (const float*)d_in[5];
    const float* Wv   = (const float*)d_in[6];
    const float* bv   = (const float*)d_in[7];
    const float* Wdec = (const float*)d_in[8];
    const float* bdec = (const float*)d_in[9];
    float* out = (float*)d_out;

    cudaFuncSetAttribute(qkv_tc, cudaFuncAttributeMaxDynamicSharedMemorySize, QKV_SMEM);
    cudaFuncSetAttribute(dec_tc, cudaFuncAttributeMaxDynamicSharedMemorySize, DEC_SMEM);

    wprep<<<13, 256>>>(Wk, Wq, Wv, Wdec);
    qkv_tc<<<dim3(MM/128, HH, NB), 256, QKV_SMEM>>>(x, bk, bq, bv);
    attn_tc<<<dim3(MM/128, HH, NB), 128>>>(x);
    dec_tc<<<NB*MM/128, 256, DEC_SMEM>>>(bdec, out);
}